// round 9
// baseline (speedup 1.0000x reference)
#include <cuda_runtime.h>
#include <cuda_bf16.h>
#include <mma.h>

using namespace nvcuda;

#define D      128
#define TWOD   256
#define MAXN   200000
#define NLAYER 5
#define TILE_M 64
#define NTHR   256

// ---------------- device scratch (allocation-free rule) ----------------
__device__ float g_h[(long)MAXN * D];
__device__ float g_agg[(long)MAXN * D];
__device__ unsigned short g_agg_hi[(long)MAXN * D];
__device__ unsigned short g_agg_lo[(long)MAXN * D];
// pre-transposed + bf16-split weights: w1t[l][n][k] = W1[l][k][n], w2t[l][n][k]=W2[l][k][n]
__device__ unsigned short g_w1t_hi[NLAYER * TWOD * D];
__device__ unsigned short g_w1t_lo[NLAYER * TWOD * D];
__device__ unsigned short g_w2t_hi[NLAYER * D * TWOD];
__device__ unsigned short g_w2t_lo[NLAYER * D * TWOD];

// ---------------- smem byte layout (total 106496 -> 2 CTAs/SM) ----------------
// sT hi/lo : [64][136] bf16 = 17408 each
// W region : hi [128][136] 34816 + lo 34816 = 69632 ; per-warp fp32 scratch aliases it
#define OFF_THI 0
#define OFF_TLO 17408
#define OFF_W   34816
#define OFF_WLO_REL 34816
#define OFF_SB1 104448
#define OFF_SB2 105472
#define OFF_SC  105984
#define SMEM_BYTES 106496

#define LDTH 136
#define LDWF 136
#define LDS_SCR 36      /* per-warp scratch ldm (fp32) */
#define SCR_STRIDE 4608 /* 32*36*4 bytes per warp */

__device__ __forceinline__ void split_pack(float a, float b,
                                           unsigned& hi, unsigned& lo) {
    __nv_bfloat16 ah = __float2bfloat16(a), bh = __float2bfloat16(b);
    __nv_bfloat16 al = __float2bfloat16(a - __bfloat162float(ah));
    __nv_bfloat16 bl = __float2bfloat16(b - __bfloat162float(bh));
    hi = (unsigned)__bfloat16_as_ushort(ah) |
         ((unsigned)__bfloat16_as_ushort(bh) << 16);
    lo = (unsigned)__bfloat16_as_ushort(al) |
         ((unsigned)__bfloat16_as_ushort(bl) << 16);
}

__device__ __forceinline__ float4 f4add(float4 a, float4 b) {
    return make_float4(a.x + b.x, a.y + b.y, a.z + b.z, a.w + b.w);
}

// ---------------------------------------------------------------------------
// prep: transpose + bf16-split all layer weights once
// ---------------------------------------------------------------------------
__global__ void prep_w(const float* __restrict__ W1, const float* __restrict__ W2) {
    int i = blockIdx.x * blockDim.x + threadIdx.x;
    int tot = NLAYER * TWOD * D;
    if (i >= tot) return;
    {   // w1t[l][n][k] = W1[l][k][n]
        int l = i / (TWOD * D), rem = i % (TWOD * D);
        int nn = rem / D, kk = rem % D;
        float v = W1[(l * D + kk) * TWOD + nn];
        __nv_bfloat16 h = __float2bfloat16(v);
        __nv_bfloat16 lo = __float2bfloat16(v - __bfloat162float(h));
        g_w1t_hi[i] = __bfloat16_as_ushort(h);
        g_w1t_lo[i] = __bfloat16_as_ushort(lo);
    }
    {   // w2t[l][n][k] = W2[l][k][n]
        int l = i / (D * TWOD), rem = i % (D * TWOD);
        int nn = rem / TWOD, kk = rem % TWOD;
        float v = W2[(l * TWOD + kk) * D + nn];
        __nv_bfloat16 h = __float2bfloat16(v);
        __nv_bfloat16 lo = __float2bfloat16(v - __bfloat162float(h));
        g_w2t_hi[i] = __bfloat16_as_ushort(h);
        g_w2t_lo[i] = __bfloat16_as_ushort(lo);
    }
}

// ---------------------------------------------------------------------------
// embed: h = xe1[x0] + xe2[x1] ; agg = h + selfloop_const(layer 0)
// ---------------------------------------------------------------------------
__global__ void embed_kernel(const int* __restrict__ x,
                             const float* __restrict__ xe1,
                             const float* __restrict__ xe2,
                             const float* __restrict__ ee1,
                             const float* __restrict__ ee2,
                             const float* __restrict__ ee3,
                             int n) {
    int idx = blockIdx.x * blockDim.x + threadIdx.x;
    if (idx >= n * (D / 4)) return;
    int node = idx >> 5;
    int j    = idx & 31;
    int a = x[node * 2 + 0];
    int c = x[node * 2 + 1];
    float4 h = f4add(((const float4*)xe1)[a * 32 + j],
                     ((const float4*)xe2)[c * 32 + j]);
    float4 cv = f4add(f4add(((const float4*)(ee1 + 4 * D))[j],
                            ((const float4*)ee2)[j]),
                      ((const float4*)ee3)[j]);
    ((float4*)g_h)[idx]   = h;
    ((float4*)g_agg)[idx] = f4add(h, cv);
}

// ---------------------------------------------------------------------------
// scatter: agg[col[e]] += h[row[e]] + edge_emb(e)   (warp/edge, red.add.v4)
// ---------------------------------------------------------------------------
__global__ void scatter_kernel(const int* __restrict__ ei,
                               const int* __restrict__ ea,
                               const float* __restrict__ e1,
                               const float* __restrict__ e2,
                               const float* __restrict__ e3,
                               int e) {
    __shared__ float s1[7 * D], s2[3 * D], s3[3 * D];
    for (int i = threadIdx.x; i < 7 * D; i += blockDim.x) s1[i] = e1[i];
    for (int i = threadIdx.x; i < 3 * D; i += blockDim.x) s2[i] = e2[i];
    for (int i = threadIdx.x; i < 3 * D; i += blockDim.x) s3[i] = e3[i];
    __syncthreads();

    int lane  = threadIdx.x & 31;
    int warp  = (blockIdx.x * blockDim.x + threadIdx.x) >> 5;
    int nwarp = (gridDim.x * blockDim.x) >> 5;

    for (int ed = warp; ed < e; ed += nwarp) {
        int row = ei[ed];
        int col = ei[e + ed];
        int bt  = ea[ed * 3 + 0];
        int bd  = ea[ed * 3 + 1];
        int bb  = ea[ed * 3 + 2];
        float4 emb = f4add(f4add(*(const float4*)&s1[bt * D + lane * 4],
                                 *(const float4*)&s2[bd * D + lane * 4]),
                           *(const float4*)&s3[bb * D + lane * 4]);
        float4 hv = *(const float4*)(g_h + (long)row * D + lane * 4);
        float4 m  = f4add(emb, hv);
        float* p  = g_agg + (long)col * D + lane * 4;
        asm volatile("red.global.add.v4.f32 [%0], {%1,%2,%3,%4};"
                     :: "l"(p), "f"(m.x), "f"(m.y), "f"(m.z), "f"(m.w)
                     : "memory");
    }
}

// ---------------------------------------------------------------------------
// split_agg: g_agg (fp32) -> g_agg_hi/lo (bf16)   [streaming, ~30us]
// ---------------------------------------------------------------------------
__global__ void split_agg(int n) {
    int idx = blockIdx.x * blockDim.x + threadIdx.x;
    if (idx >= n * (D / 4)) return;
    float4 v = ((const float4*)g_agg)[idx];
    unsigned h0, l0, h1, l1;
    split_pack(v.x, v.y, h0, l0);
    split_pack(v.z, v.w, h1, l1);
    ((uint2*)g_agg_hi)[idx] = make_uint2(h0, h1);
    ((uint2*)g_agg_lo)[idx] = make_uint2(l0, l1);
}

// ---------------------------------------------------------------------------
// wmma fused GIN MLP v3: A frags from gmem, full-K W slices, warp-scratch convert
// ---------------------------------------------------------------------------
__global__ void __launch_bounds__(NTHR, 2)
mlp_wmma_kernel(int l, int last,
                const float* __restrict__ b1g, const float* __restrict__ b2g,
                const float* __restrict__ ee1, const float* __restrict__ ee2,
                const float* __restrict__ ee3,
                float* __restrict__ out, int n) {
    extern __shared__ char smem[];
    __nv_bfloat16* sThi = (__nv_bfloat16*)(smem + OFF_THI);
    __nv_bfloat16* sTlo = (__nv_bfloat16*)(smem + OFF_TLO);
    __nv_bfloat16* sWhi = (__nv_bfloat16*)(smem + OFF_W);
    __nv_bfloat16* sWlo = (__nv_bfloat16*)(smem + OFF_W + OFF_WLO_REL);
    float* sb1 = (float*)(smem + OFF_SB1);
    float* sb2 = (float*)(smem + OFF_SB2);
    float* sc  = (float*)(smem + OFF_SC);

    int tid  = threadIdx.x;
    int wid  = tid >> 5;
    int lane = tid & 31;
    int wr = wid >> 2, wc = wid & 3;   // 2x4 warp grid, 32x32 warp tiles
    int row0 = blockIdx.x * TILE_M;
    float* scr = (float*)(smem + OFF_W + wid * SCR_STRIDE);  // per-warp 32x36 fp32

    // biases + next-layer self-loop const
    for (int i = tid; i < TWOD; i += NTHR) sb1[i] = b1g[l * TWOD + i];
    if (tid < D) {
        sb2[tid] = b2g[l * D + tid];
        float cv = 0.f;
        if (!last) {
            int ln = l + 1;
            cv = ee1[(ln * 7 + 4) * D + tid] + ee2[ln * 3 * D + tid]
               + ee3[ln * 3 * D + tid];
        }
        sc[tid] = cv;
    }

    const __nv_bfloat16* gAhi = (const __nv_bfloat16*)g_agg_hi + (long)row0 * D;
    const __nv_bfloat16* gAlo = (const __nv_bfloat16*)g_agg_lo + (long)row0 * D;

    wmma::fragment<wmma::accumulator, 16, 16, 16, float> acc2[2][2];
#pragma unroll
    for (int i = 0; i < 2; ++i)
#pragma unroll
        for (int j = 0; j < 2; ++j) wmma::fill_fragment(acc2[i][j], 0.f);

    // ================= column-half loop =================
    for (int h = 0; h < 2; ++h) {
        // (a) protect W region (prev readers / scratch users done)
        __syncthreads();
        // (b) load W1 slice [128n][128k] hi/lo, full K
        for (int i = tid; i < 2048; i += NTHR) {        // 2048 = 128*128/8
            int nn = i >> 4, k8 = i & 15;
            long src = ((long)(l * TWOD + h * 128 + nn)) * D + k8 * 8;
            *(uint4*)(sWhi + nn * LDWF + k8 * 8) = *(const uint4*)(g_w1t_hi + src);
            *(uint4*)(sWlo + nn * LDWF + k8 * 8) = *(const uint4*)(g_w1t_lo + src);
        }
        __syncthreads();

        // (d) stage 1: C1h[64,128] = A @ W1h   (A frags straight from gmem)
        wmma::fragment<wmma::accumulator, 16, 16, 16, float> acc1[2][2];
#pragma unroll
        for (int i = 0; i < 2; ++i)
#pragma unroll
            for (int j = 0; j < 2; ++j) wmma::fill_fragment(acc1[i][j], 0.f);

#pragma unroll
        for (int ks = 0; ks < 8; ++ks) {
            wmma::fragment<wmma::matrix_a, 16, 16, 16, __nv_bfloat16, wmma::row_major> ahi[2], alo[2];
            wmma::fragment<wmma::matrix_b, 16, 16, 16, __nv_bfloat16, wmma::col_major> bhi[2], blo[2];
#pragma unroll
            for (int i = 0; i < 2; ++i) {
                long off = (long)(wr * 32 + i * 16) * D + ks * 16;
                wmma::load_matrix_sync(ahi[i], gAhi + off, D);
                wmma::load_matrix_sync(alo[i], gAlo + off, D);
            }
#pragma unroll
            for (int j = 0; j < 2; ++j) {
                const __nv_bfloat16* pb = sWhi + (wc * 32 + j * 16) * LDWF + ks * 16;
                wmma::load_matrix_sync(bhi[j], pb, LDWF);
                wmma::load_matrix_sync(blo[j], pb + OFF_WLO_REL / 2, LDWF);
            }
#pragma unroll
            for (int i = 0; i < 2; ++i)
#pragma unroll
                for (int j = 0; j < 2; ++j) {
                    wmma::mma_sync(acc1[i][j], ahi[i], bhi[j], acc1[i][j]);
                    wmma::mma_sync(acc1[i][j], ahi[i], blo[j], acc1[i][j]);
                    wmma::mma_sync(acc1[i][j], alo[i], bhi[j], acc1[i][j]);
                }
        }

        // (e) all W1 reads done -> scratch (aliases W) is safe
        __syncthreads();
        // (f) per-warp: acc1 -> scratch -> convert -> T-half (disjoint regions)
#pragma unroll
        for (int i = 0; i < 2; ++i)
#pragma unroll
            for (int j = 0; j < 2; ++j)
                wmma::store_matrix_sync(scr + (i * 16) * LDS_SCR + j * 16,
                                        acc1[i][j], LDS_SCR, wmma::mem_row_major);
        __syncwarp();
        {
            float bb = sb1[h * 128 + wc * 32 + lane];
#pragma unroll
            for (int rr = 0; rr < 32; ++rr) {
                float t = fmaxf(scr[rr * LDS_SCR + lane] + bb, 0.f);
                __nv_bfloat16 th = __float2bfloat16(t);
                __nv_bfloat16 tl = __float2bfloat16(t - __bfloat162float(th));
                int r = wr * 32 + rr, c = wc * 32 + lane;
                sThi[r * LDTH + c] = th;
                sTlo[r * LDTH + c] = tl;
            }
        }
        // (g) scratch reads + T writes complete before W2 load / T frag reads
        __syncthreads();
        // (h) load W2 slice [128n][128k of k-range h*128..] hi/lo
        for (int i = tid; i < 2048; i += NTHR) {
            int nn = i >> 4, k8 = i & 15;
            long src = ((long)(l * D + nn)) * TWOD + h * 128 + k8 * 8;
            *(uint4*)(sWhi + nn * LDWF + k8 * 8) = *(const uint4*)(g_w2t_hi + src);
            *(uint4*)(sWlo + nn * LDWF + k8 * 8) = *(const uint4*)(g_w2t_lo + src);
        }
        __syncthreads();

        // (j) stage 2: C2 += Th @ W2h
#pragma unroll
        for (int ks = 0; ks < 8; ++ks) {
            wmma::fragment<wmma::matrix_a, 16, 16, 16, __nv_bfloat16, wmma::row_major> ahi[2], alo[2];
            wmma::fragment<wmma::matrix_b, 16, 16, 16, __nv_bfloat16, wmma::col_major> bhi[2], blo[2];
#pragma unroll
            for (int i = 0; i < 2; ++i) {
                const __nv_bfloat16* pa = sThi + (wr * 32 + i * 16) * LDTH + ks * 16;
                wmma::load_matrix_sync(ahi[i], pa, LDTH);
                wmma::load_matrix_sync(alo[i], pa + (OFF_TLO - OFF_THI) / 2, LDTH);
            }
#pragma unroll
            for (int j = 0; j < 2; ++j) {
                const __nv_bfloat16* pb = sWhi + (wc * 32 + j * 16) * LDWF + ks * 16;
                wmma::load_matrix_sync(bhi[j], pb, LDWF);
                wmma::load_matrix_sync(blo[j], pb + OFF_WLO_REL / 2, LDWF);
            }
#pragma unroll
            for (int i = 0; i < 2; ++i)
#pragma unroll
                for (int j = 0; j < 2; ++j) {
                    wmma::mma_sync(acc2[i][j], ahi[i], bhi[j], acc2[i][j]);
                    wmma::mma_sync(acc2[i][j], ahi[i], blo[j], acc2[i][j]);
                    wmma::mma_sync(acc2[i][j], alo[i], bhi[j], acc2[i][j]);
                }
        }
    }

    // (k) all stage2 W reads done
    __syncthreads();
    // (l) per-warp epilogue: acc2 -> scratch -> bias -> gmem
#pragma unroll
    for (int i = 0; i < 2; ++i)
#pragma unroll
        for (int j = 0; j < 2; ++j)
            wmma::store_matrix_sync(scr + (i * 16) * LDS_SCR + j * 16,
                                    acc2[i][j], LDS_SCR, wmma::mem_row_major);
    __syncwarp();
    {
        int c = wc * 32 + lane;
        float bb = sb2[c];
        float cv = sc[c];
#pragma unroll
        for (int rr = 0; rr < 32; ++rr) {
            long grow = (long)row0 + wr * 32 + rr;
            if (grow >= n) continue;
            float o = scr[rr * LDS_SCR + lane] + bb;
            long off = grow * D + c;
            if (last) {
                out[off] = o;
            } else {
                float hv = fmaxf(o, 0.f);
                g_h[off]   = hv;
                g_agg[off] = hv + cv;
            }
        }
    }
}

// ---------------------------------------------------------------------------
extern "C" void kernel_launch(void* const* d_in, const int* in_sizes, int n_in,
                              void* d_out, int out_size) {
    const int*   x   = (const int*)d_in[0];
    const int*   ei  = (const int*)d_in[1];
    const int*   ea  = (const int*)d_in[2];
    const float* xe1 = (const float*)d_in[3];
    const float* xe2 = (const float*)d_in[4];
    const float* ee1 = (const float*)d_in[5];
    const float* ee2 = (const float*)d_in[6];
    const float* ee3 = (const float*)d_in[7];
    const float* W1  = (const float*)d_in[8];
    const float* b1  = (const float*)d_in[9];
    const float* W2  = (const float*)d_in[10];
    const float* b2  = (const float*)d_in[11];
    float* out = (float*)d_out;
    int n = in_sizes[0] / 2;   // x is [N,2]
    int e = in_sizes[1] / 2;   // edge_index is [2,E]

    cudaFuncSetAttribute(mlp_wmma_kernel,
                         cudaFuncAttributeMaxDynamicSharedMemorySize, SMEM_BYTES);

    prep_w<<<(NLAYER * TWOD * D + 255) / 256, 256>>>(W1, W2);
    embed_kernel<<<(n * (D / 4) + 255) / 256, 256>>>(x, xe1, xe2, ee1, ee2, ee3, n);

    int ntiles = (n + TILE_M - 1) / TILE_M;
    int nsplit = (n * (D / 4) + 255) / 256;
    for (int l = 0; l < NLAYER; ++l) {
        scatter_kernel<<<2368, 256>>>(ei, ea,
                                      ee1 + (long)l * 7 * D,
                                      ee2 + (long)l * 3 * D,
                                      ee3 + (long)l * 3 * D, e);
        split_agg<<<nsplit, 256>>>(n);
        int last = (l == NLAYER - 1);
        mlp_wmma_kernel<<<ntiles, NTHR, SMEM_BYTES>>>(
            l, last, b1, b2, ee1, ee2, ee3, out, n);
    }
}

// round 11
// speedup vs baseline: 2.0041x; 2.0041x over previous
#include <cuda_runtime.h>
#include <cuda_fp16.h>
#include <mma.h>

using namespace nvcuda;

#define D      128
#define TWOD   256
#define MAXN   200000
#define NLAYER 5
#define TILE_M 64
#define NTHR   256

// ---------------- device scratch (allocation-free rule) ----------------
__device__ float g_h[(long)MAXN * D];
__device__ float g_agg[(long)MAXN * D];
// pre-transposed fp16 weights: w1t[l][n][k] = W1[l][k][n], w2t[l][n][k] = W2[l][k][n]
__device__ __half g_w1t[NLAYER * TWOD * D];
__device__ __half g_w2t[NLAYER * D * TWOD];

// ---------------- smem byte layout (total 73728 -> 2 CTAs/SM) ----------------
// sA : [64][136] fp16 = 17408
// sT : [64][136] fp16 = 17408   (one column-half of T at a time)
// W  : [128][136] fp16 = 34816, region padded to 36864 for per-warp fp32 scratch
#define OFF_A   0
#define OFF_T   17408
#define OFF_W   34816
#define OFF_SB1 71680
#define OFF_SB2 72704
#define OFF_SC  73216
#define SMEM_BYTES 73728

#define LDA  136
#define LDTH 136
#define LDWF 136
#define LDS_SCR 36      /* per-warp scratch ldm (fp32) */
#define SCR_STRIDE 4608 /* 32*36*4 bytes per warp */

__device__ __forceinline__ float4 f4add(float4 a, float4 b) {
    return make_float4(a.x + b.x, a.y + b.y, a.z + b.z, a.w + b.w);
}

// ---------------------------------------------------------------------------
// prep: transpose weights to [n][k] fp16 once
// ---------------------------------------------------------------------------
__global__ void prep_w(const float* __restrict__ W1, const float* __restrict__ W2) {
    int i = blockIdx.x * blockDim.x + threadIdx.x;
    int tot = NLAYER * TWOD * D;
    if (i >= tot) return;
    {   // w1t[l][n][k] = W1[l][k][n]
        int l = i / (TWOD * D), rem = i % (TWOD * D);
        int nn = rem / D, kk = rem % D;
        g_w1t[i] = __float2half_rn(W1[(l * D + kk) * TWOD + nn]);
    }
    {   // w2t[l][n][k] = W2[l][k][n]
        int l = i / (D * TWOD), rem = i % (D * TWOD);
        int nn = rem / TWOD, kk = rem % TWOD;
        g_w2t[i] = __float2half_rn(W2[(l * TWOD + kk) * D + nn]);
    }
}

// ---------------------------------------------------------------------------
// embed: h = xe1[x0] + xe2[x1] ; agg = h + selfloop_const(layer 0)
// ---------------------------------------------------------------------------
__global__ void embed_kernel(const int* __restrict__ x,
                             const float* __restrict__ xe1,
                             const float* __restrict__ xe2,
                             const float* __restrict__ ee1,
                             const float* __restrict__ ee2,
                             const float* __restrict__ ee3,
                             int n) {
    int idx = blockIdx.x * blockDim.x + threadIdx.x;
    if (idx >= n * (D / 4)) return;
    int node = idx >> 5;
    int j    = idx & 31;
    int a = x[node * 2 + 0];
    int c = x[node * 2 + 1];
    float4 h = f4add(((const float4*)xe1)[a * 32 + j],
                     ((const float4*)xe2)[c * 32 + j]);
    float4 cv = f4add(f4add(((const float4*)(ee1 + 4 * D))[j],
                            ((const float4*)ee2)[j]),
                      ((const float4*)ee3)[j]);
    ((float4*)g_h)[idx]   = h;
    ((float4*)g_agg)[idx] = f4add(h, cv);
}

// ---------------------------------------------------------------------------
// scatter: agg[col[e]] += h[row[e]] + edge_emb(e)   (warp/edge, red.add.v4)
// ---------------------------------------------------------------------------
__global__ void scatter_kernel(const int* __restrict__ ei,
                               const int* __restrict__ ea,
                               const float* __restrict__ e1,
                               const float* __restrict__ e2,
                               const float* __restrict__ e3,
                               int e) {
    __shared__ float s1[7 * D], s2[3 * D], s3[3 * D];
    for (int i = threadIdx.x; i < 7 * D; i += blockDim.x) s1[i] = e1[i];
    for (int i = threadIdx.x; i < 3 * D; i += blockDim.x) s2[i] = e2[i];
    for (int i = threadIdx.x; i < 3 * D; i += blockDim.x) s3[i] = e3[i];
    __syncthreads();

    int lane  = threadIdx.x & 31;
    int warp  = (blockIdx.x * blockDim.x + threadIdx.x) >> 5;
    int nwarp = (gridDim.x * blockDim.x) >> 5;

    for (int ed = warp; ed < e; ed += nwarp) {
        int row = ei[ed];
        int col = ei[e + ed];
        int bt  = ea[ed * 3 + 0];
        int bd  = ea[ed * 3 + 1];
        int bb  = ea[ed * 3 + 2];
        float4 emb = f4add(f4add(*(const float4*)&s1[bt * D + lane * 4],
                                 *(const float4*)&s2[bd * D + lane * 4]),
                           *(const float4*)&s3[bb * D + lane * 4]);
        float4 hv = *(const float4*)(g_h + (long)row * D + lane * 4);
        float4 m  = f4add(emb, hv);
        float* p  = g_agg + (long)col * D + lane * 4;
        asm volatile("red.global.add.v4.f32 [%0], {%1,%2,%3,%4};"
                     :: "l"(p), "f"(m.x), "f"(m.y), "f"(m.z), "f"(m.w)
                     : "memory");
    }
}

// ---------------------------------------------------------------------------
// wmma fused GIN MLP v4: fp16 single-pass, column-half fusion, full-K W slices
// ---------------------------------------------------------------------------
__global__ void __launch_bounds__(NTHR, 2)
mlp_wmma_kernel(int l, int last,
                const float* __restrict__ b1g, const float* __restrict__ b2g,
                const float* __restrict__ ee1, const float* __restrict__ ee2,
                const float* __restrict__ ee3,
                float* __restrict__ out, int n) {
    extern __shared__ char smem[];
    __half* sA = (__half*)(smem + OFF_A);
    __half* sT = (__half*)(smem + OFF_T);
    __half* sW = (__half*)(smem + OFF_W);
    float* sb1 = (float*)(smem + OFF_SB1);
    float* sb2 = (float*)(smem + OFF_SB2);
    float* sc  = (float*)(smem + OFF_SC);

    int tid  = threadIdx.x;
    int wid  = tid >> 5;
    int lane = tid & 31;
    int wr = wid >> 2, wc = wid & 3;   // 2x4 warp grid, 32x32 warp tiles
    int row0 = blockIdx.x * TILE_M;
    float* scr = (float*)(smem + OFF_W + wid * SCR_STRIDE);  // per-warp 32x36 fp32

    // biases + next-layer self-loop const
    for (int i = tid; i < TWOD; i += NTHR) sb1[i] = b1g[l * TWOD + i];
    if (tid < D) {
        sb2[tid] = b2g[l * D + tid];
        float cv = 0.f;
        if (!last) {
            int ln = l + 1;
            cv = ee1[(ln * 7 + 4) * D + tid] + ee2[ln * 3 * D + tid]
               + ee3[ln * 3 * D + tid];
        }
        sc[tid] = cv;
    }

    // ---- load A tile fp32 -> fp16 smem ----
    for (int i = tid; i < TILE_M * (D / 4); i += NTHR) {  // 2048
        int r = i >> 5, c4 = i & 31;
        float4 v = make_float4(0.f, 0.f, 0.f, 0.f);
        if (row0 + r < n)
            v = *(const float4*)(g_agg + ((long)(row0 + r)) * D + c4 * 4);
        __half2 p0 = __floats2half2_rn(v.x, v.y);
        __half2 p1 = __floats2half2_rn(v.z, v.w);
        *(__half2*)(sA + r * LDA + c4 * 4)     = p0;
        *(__half2*)(sA + r * LDA + c4 * 4 + 2) = p1;
    }

    wmma::fragment<wmma::accumulator, 16, 16, 16, float> acc2[2][2];
#pragma unroll
    for (int i = 0; i < 2; ++i)
#pragma unroll
        for (int j = 0; j < 2; ++j) wmma::fill_fragment(acc2[i][j], 0.f);

    // ================= column-half loop =================
    for (int h = 0; h < 2; ++h) {
        // (a) protect W region (prev readers / scratch users / A writes done)
        __syncthreads();
        // (b) load W1 half-slice [128n][128k] fp16, full K
        for (int i = tid; i < 2048; i += NTHR) {        // 128*128/8
            int nn = i >> 4, k8 = i & 15;
            long src = ((long)(l * TWOD + h * 128 + nn)) * D + k8 * 8;
            *(uint4*)(sW + nn * LDWF + k8 * 8) = *(const uint4*)(g_w1t + src);
        }
        __syncthreads();

        // (d) stage 1: C1h[64,128] = A @ W1h
        wmma::fragment<wmma::accumulator, 16, 16, 16, float> acc1[2][2];
#pragma unroll
        for (int i = 0; i < 2; ++i)
#pragma unroll
            for (int j = 0; j < 2; ++j) wmma::fill_fragment(acc1[i][j], 0.f);

#pragma unroll
        for (int ks = 0; ks < 8; ++ks) {
            wmma::fragment<wmma::matrix_a, 16, 16, 16, __half, wmma::row_major> af[2];
            wmma::fragment<wmma::matrix_b, 16, 16, 16, __half, wmma::col_major> bf[2];
#pragma unroll
            for (int i = 0; i < 2; ++i)
                wmma::load_matrix_sync(af[i], sA + (wr * 32 + i * 16) * LDA + ks * 16, LDA);
#pragma unroll
            for (int j = 0; j < 2; ++j)
                wmma::load_matrix_sync(bf[j], sW + (wc * 32 + j * 16) * LDWF + ks * 16, LDWF);
#pragma unroll
            for (int i = 0; i < 2; ++i)
#pragma unroll
                for (int j = 0; j < 2; ++j)
                    wmma::mma_sync(acc1[i][j], af[i], bf[j], acc1[i][j]);
        }

        // (e) all W1 reads done -> scratch (aliases W) is safe
        __syncthreads();
        // (f) per-warp: acc1 -> scratch -> relu+bias -> T-half fp16
#pragma unroll
        for (int i = 0; i < 2; ++i)
#pragma unroll
            for (int j = 0; j < 2; ++j)
                wmma::store_matrix_sync(scr + (i * 16) * LDS_SCR + j * 16,
                                        acc1[i][j], LDS_SCR, wmma::mem_row_major);
        __syncwarp();
        {
            float bb = sb1[h * 128 + wc * 32 + lane];
#pragma unroll
            for (int rr = 0; rr < 32; ++rr) {
                float t = fmaxf(scr[rr * LDS_SCR + lane] + bb, 0.f);
                sT[(wr * 32 + rr) * LDTH + wc * 32 + lane] = __float2half_rn(t);
            }
        }
        // (g) scratch reads + T writes complete before W2 load / T frag reads
        __syncthreads();
        // (h) load W2 slice [128n][k-range h*128..+128] fp16
        for (int i = tid; i < 2048; i += NTHR) {
            int nn = i >> 4, k8 = i & 15;
            long src = ((long)(l * D + nn)) * TWOD + h * 128 + k8 * 8;
            *(uint4*)(sW + nn * LDWF + k8 * 8) = *(const uint4*)(g_w2t + src);
        }
        __syncthreads();

        // (j) stage 2: C2 += Th @ W2h
#pragma unroll
        for (int ks = 0; ks < 8; ++ks) {
            wmma::fragment<wmma::matrix_a, 16, 16, 16, __half, wmma::row_major> af[2];
            wmma::fragment<wmma::matrix_b, 16, 16, 16, __half, wmma::col_major> bf[2];
#pragma unroll
            for (int i = 0; i < 2; ++i)
                wmma::load_matrix_sync(af[i], sT + (wr * 32 + i * 16) * LDTH + ks * 16, LDTH);
#pragma unroll
            for (int j = 0; j < 2; ++j)
                wmma::load_matrix_sync(bf[j], sW + (wc * 32 + j * 16) * LDWF + ks * 16, LDWF);
#pragma unroll
            for (int i = 0; i < 2; ++i)
#pragma unroll
                for (int j = 0; j < 2; ++j)
                    wmma::mma_sync(acc2[i][j], af[i], bf[j], acc2[i][j]);
        }
    }

    // (k) all stage2 W reads done
    __syncthreads();
    // (l) per-warp epilogue: acc2 -> scratch -> bias -> gmem
#pragma unroll
    for (int i = 0; i < 2; ++i)
#pragma unroll
        for (int j = 0; j < 2; ++j)
            wmma::store_matrix_sync(scr + (i * 16) * LDS_SCR + j * 16,
                                    acc2[i][j], LDS_SCR, wmma::mem_row_major);
    __syncwarp();
    {
        int c = wc * 32 + lane;
        float bb = sb2[c];
        float cv = sc[c];
#pragma unroll
        for (int rr = 0; rr < 32; ++rr) {
            long grow = (long)row0 + wr * 32 + rr;
            if (grow >= n) continue;
            float o = scr[rr * LDS_SCR + lane] + bb;
            long off = grow * D + c;
            if (last) {
                out[off] = o;
            } else {
                float hv = fmaxf(o, 0.f);
                g_h[off]   = hv;
                g_agg[off] = hv + cv;
            }
        }
    }
}

// ---------------------------------------------------------------------------
extern "C" void kernel_launch(void* const* d_in, const int* in_sizes, int n_in,
                              void* d_out, int out_size) {
    const int*   x   = (const int*)d_in[0];
    const int*   ei  = (const int*)d_in[1];
    const int*   ea  = (const int*)d_in[2];
    const float* xe1 = (const float*)d_in[3];
    const float* xe2 = (const float*)d_in[4];
    const float* ee1 = (const float*)d_in[5];
    const float* ee2 = (const float*)d_in[6];
    const float* ee3 = (const float*)d_in[7];
    const float* W1  = (const float*)d_in[8];
    const float* b1  = (const float*)d_in[9];
    const float* W2  = (const float*)d_in[10];
    const float* b2  = (const float*)d_in[11];
    float* out = (float*)d_out;
    int n = in_sizes[0] / 2;   // x is [N,2]
    int e = in_sizes[1] / 2;   // edge_index is [2,E]

    cudaFuncSetAttribute(mlp_wmma_kernel,
                         cudaFuncAttributeMaxDynamicSharedMemorySize, SMEM_BYTES);

    prep_w<<<(NLAYER * TWOD * D + 255) / 256, 256>>>(W1, W2);
    embed_kernel<<<(n * (D / 4) + 255) / 256, 256>>>(x, xe1, xe2, ee1, ee2, ee3, n);

    int ntiles = (n + TILE_M - 1) / TILE_M;
    for (int l = 0; l < NLAYER; ++l) {
        scatter_kernel<<<2368, 256>>>(ei, ea,
                                      ee1 + (long)l * 7 * D,
                                      ee2 + (long)l * 3 * D,
                                      ee3 + (long)l * 3 * D, e);
        int last = (l == NLAYER - 1);
        mlp_wmma_kernel<<<ntiles, NTHR, SMEM_BYTES>>>(
            l, last, b1, b2, ee1, ee2, ee3, out, n);
    }
}

// round 13
// speedup vs baseline: 2.2030x; 1.0992x over previous
#include <cuda_runtime.h>
#include <cuda_fp16.h>
#include <mma.h>

using namespace nvcuda;

#define D      128
#define TWOD   256
#define MAXN   200000
#define NLAYER 5
#define TILE_M 64
#define NTHR   256

// ---------------- device scratch (allocation-free rule) ----------------
__device__ float g_h[(long)MAXN * D];
__device__ float g_agg[(long)MAXN * D];
// pre-transposed fp16 weights: w1t[l][n][k] = W1[l][k][n], w2t[l][n][k] = W2[l][k][n]
__device__ __half g_w1t[NLAYER * TWOD * D];
__device__ __half g_w2t[NLAYER * D * TWOD];

// ---------------- smem byte layout (total 73728 -> 3 CTAs/SM) ----------------
// R0: sA fp16 [64][136] = 17408 ; reused as T1 after stage1 h1
// R1: T0 fp16 [64][136] = 17408
// R2: W slice fp16 [128][136] = 34816, padded to 36864 for per-warp fp32 scratch
#define OFF_A   0
#define OFF_T0  17408
#define OFF_W   34816
#define OFF_SB1 71680
#define OFF_SB2 72704
#define OFF_SC  73216
#define SMEM_BYTES 73728

#define LDA  136
#define LDTH 136
#define LDWF 136
#define LDS_SCR 36      /* per-warp scratch ldm (fp32), 144B multiple-of-16 */
#define SCR_STRIDE 4608 /* 32*36*4 bytes per warp */

__device__ __forceinline__ float4 f4add(float4 a, float4 b) {
    return make_float4(a.x + b.x, a.y + b.y, a.z + b.z, a.w + b.w);
}

// ---------------------------------------------------------------------------
// prep: transpose weights to [n][k] fp16 once
// ---------------------------------------------------------------------------
__global__ void prep_w(const float* __restrict__ W1, const float* __restrict__ W2) {
    int i = blockIdx.x * blockDim.x + threadIdx.x;
    int tot = NLAYER * TWOD * D;
    if (i >= tot) return;
    {   // w1t[l][n][k] = W1[l][k][n]
        int l = i / (TWOD * D), rem = i % (TWOD * D);
        int nn = rem / D, kk = rem % D;
        g_w1t[i] = __float2half_rn(W1[(l * D + kk) * TWOD + nn]);
    }
    {   // w2t[l][n][k] = W2[l][k][n]
        int l = i / (D * TWOD), rem = i % (D * TWOD);
        int nn = rem / TWOD, kk = rem % TWOD;
        g_w2t[i] = __float2half_rn(W2[(l * TWOD + kk) * D + nn]);
    }
}

// ---------------------------------------------------------------------------
// embed: h = xe1[x0] + xe2[x1] ; agg = h + selfloop_const(layer 0)
// ---------------------------------------------------------------------------
__global__ void embed_kernel(const int* __restrict__ x,
                             const float* __restrict__ xe1,
                             const float* __restrict__ xe2,
                             const float* __restrict__ ee1,
                             const float* __restrict__ ee2,
                             const float* __restrict__ ee3,
                             int n) {
    int idx = blockIdx.x * blockDim.x + threadIdx.x;
    if (idx >= n * (D / 4)) return;
    int node = idx >> 5;
    int j    = idx & 31;
    int a = x[node * 2 + 0];
    int c = x[node * 2 + 1];
    float4 h = f4add(((const float4*)xe1)[a * 32 + j],
                     ((const float4*)xe2)[c * 32 + j]);
    float4 cv = f4add(f4add(((const float4*)(ee1 + 4 * D))[j],
                            ((const float4*)ee2)[j]),
                      ((const float4*)ee3)[j]);
    ((float4*)g_h)[idx]   = h;
    ((float4*)g_agg)[idx] = f4add(h, cv);
}

// ---------------------------------------------------------------------------
// scatter: agg[col[e]] += h[row[e]] + edge_emb(e)   (warp/edge, red.add.v4)
// ---------------------------------------------------------------------------
__global__ void scatter_kernel(const int* __restrict__ ei,
                               const int* __restrict__ ea,
                               const float* __restrict__ e1,
                               const float* __restrict__ e2,
                               const float* __restrict__ e3,
                               int e) {
    __shared__ float s1[7 * D], s2[3 * D], s3[3 * D];
    for (int i = threadIdx.x; i < 7 * D; i += blockDim.x) s1[i] = e1[i];
    for (int i = threadIdx.x; i < 3 * D; i += blockDim.x) s2[i] = e2[i];
    for (int i = threadIdx.x; i < 3 * D; i += blockDim.x) s3[i] = e3[i];
    __syncthreads();

    int lane  = threadIdx.x & 31;
    int warp  = (blockIdx.x * blockDim.x + threadIdx.x) >> 5;
    int nwarp = (gridDim.x * blockDim.x) >> 5;

    for (int ed = warp; ed < e; ed += nwarp) {
        int row = ei[ed];
        int col = ei[e + ed];
        int bt  = ea[ed * 3 + 0];
        int bd  = ea[ed * 3 + 1];
        int bb  = ea[ed * 3 + 2];
        float4 emb = f4add(f4add(*(const float4*)&s1[bt * D + lane * 4],
                                 *(const float4*)&s2[bd * D + lane * 4]),
                           *(const float4*)&s3[bb * D + lane * 4]);
        float4 hv = *(const float4*)(g_h + (long)row * D + lane * 4);
        float4 m  = f4add(emb, hv);
        float* p  = g_agg + (long)col * D + lane * 4;
        asm volatile("red.global.add.v4.f32 [%0], {%1,%2,%3,%4};"
                     :: "l"(p), "f"(m.x), "f"(m.y), "f"(m.z), "f"(m.w)
                     : "memory");
    }
}

// ---------------------------------------------------------------------------
// wmma fused GIN MLP v5: fp16 single-pass, acc-split phases, 3 CTAs/SM
// ---------------------------------------------------------------------------
__global__ void __launch_bounds__(NTHR, 3)
mlp_wmma_kernel(int l, int last,
                const float* __restrict__ b1g, const float* __restrict__ b2g,
                const float* __restrict__ ee1, const float* __restrict__ ee2,
                const float* __restrict__ ee3,
                float* __restrict__ out, int n) {
    extern __shared__ char smem[];
    __half* sA = (__half*)(smem + OFF_A);     // A tile; becomes T1 after stage1 h1
    __half* sT0 = (__half*)(smem + OFF_T0);
    __half* sW = (__half*)(smem + OFF_W);
    float* sb1 = (float*)(smem + OFF_SB1);
    float* sb2 = (float*)(smem + OFF_SB2);
    float* sc  = (float*)(smem + OFF_SC);

    int tid  = threadIdx.x;
    int wid  = tid >> 5;
    int lane = tid & 31;
    int wr = wid >> 2, wc = wid & 3;   // 2x4 warp grid, 32x32 warp tiles
    int row0 = blockIdx.x * TILE_M;
    float* scr = (float*)(smem + OFF_W + wid * SCR_STRIDE);  // per-warp 32x36 fp32

    // biases + next-layer self-loop const
    for (int i = tid; i < TWOD; i += NTHR) sb1[i] = b1g[l * TWOD + i];
    if (tid < D) {
        sb2[tid] = b2g[l * D + tid];
        float cv = 0.f;
        if (!last) {
            int ln = l + 1;
            cv = ee1[(ln * 7 + 4) * D + tid] + ee2[ln * 3 * D + tid]
               + ee3[ln * 3 * D + tid];
        }
        sc[tid] = cv;
    }

    // ---- load A tile fp32 -> fp16 smem ----
    for (int i = tid; i < TILE_M * (D / 4); i += NTHR) {  // 2048
        int r = i >> 5, c4 = i & 31;
        float4 v = make_float4(0.f, 0.f, 0.f, 0.f);
        if (row0 + r < n)
            v = *(const float4*)(g_agg + ((long)(row0 + r)) * D + c4 * 4);
        __half2 p0 = __floats2half2_rn(v.x, v.y);
        __half2 p1 = __floats2half2_rn(v.z, v.w);
        *(__half2*)(sA + r * LDA + c4 * 4)     = p0;
        *(__half2*)(sA + r * LDA + c4 * 4 + 2) = p1;
    }

    // ================= PHASE 1: T = relu(A @ W1 + b1), half by half =========
    for (int h = 0; h < 2; ++h) {
        // load W1 half-slice [128n][128k] (first iter also covered by A-load sync)
        if (h == 0) {
            for (int i = tid; i < 2048; i += NTHR) {
                int nn = i >> 4, k8 = i & 15;
                long src = ((long)(l * TWOD + nn)) * D + k8 * 8;
                *(uint4*)(sW + nn * LDWF + k8 * 8) = *(const uint4*)(g_w1t + src);
            }
        } else {
            for (int i = tid; i < 2048; i += NTHR) {
                int nn = i >> 4, k8 = i & 15;
                long src = ((long)(l * TWOD + 128 + nn)) * D + k8 * 8;
                *(uint4*)(sW + nn * LDWF + k8 * 8) = *(const uint4*)(g_w1t + src);
            }
        }
        __syncthreads();   // W (+A on first iter) visible

        wmma::fragment<wmma::accumulator, 16, 16, 16, float> acc1[2][2];
#pragma unroll
        for (int i = 0; i < 2; ++i)
#pragma unroll
            for (int j = 0; j < 2; ++j) wmma::fill_fragment(acc1[i][j], 0.f);

#pragma unroll
        for (int ks = 0; ks < 8; ++ks) {
            wmma::fragment<wmma::matrix_a, 16, 16, 16, __half, wmma::row_major> af[2];
            wmma::fragment<wmma::matrix_b, 16, 16, 16, __half, wmma::col_major> bf[2];
#pragma unroll
            for (int i = 0; i < 2; ++i)
                wmma::load_matrix_sync(af[i], sA + (wr * 32 + i * 16) * LDA + ks * 16, LDA);
#pragma unroll
            for (int j = 0; j < 2; ++j)
                wmma::load_matrix_sync(bf[j], sW + (wc * 32 + j * 16) * LDWF + ks * 16, LDWF);
#pragma unroll
            for (int i = 0; i < 2; ++i)
#pragma unroll
                for (int j = 0; j < 2; ++j)
                    wmma::mma_sync(acc1[i][j], af[i], bf[j], acc1[i][j]);
        }

        __syncthreads();   // all W1h (and, for h=1, all sA) reads done

        // acc1 -> per-warp scratch (aliases W) -> relu+bias -> T half
        __half* sTd = (h == 0) ? sT0 : sA;   // T1 aliases sA (sA dead after h1 MMAs)
#pragma unroll
        for (int i = 0; i < 2; ++i)
#pragma unroll
            for (int j = 0; j < 2; ++j)
                wmma::store_matrix_sync(scr + (i * 16) * LDS_SCR + j * 16,
                                        acc1[i][j], LDS_SCR, wmma::mem_row_major);
        __syncwarp();
        {
            float bb = sb1[h * 128 + wc * 32 + lane];
#pragma unroll
            for (int rr = 0; rr < 32; ++rr) {
                float t = fmaxf(scr[rr * LDS_SCR + lane] + bb, 0.f);
                sTd[(wr * 32 + rr) * LDTH + wc * 32 + lane] = __float2half_rn(t);
            }
        }
        __syncthreads();   // scratch reads + T writes done before next W load
    }

    // ================= PHASE 2: C2 = T @ W2, k-slice by k-slice =============
    wmma::fragment<wmma::accumulator, 16, 16, 16, float> acc2[2][2];
#pragma unroll
    for (int i = 0; i < 2; ++i)
#pragma unroll
        for (int j = 0; j < 2; ++j) wmma::fill_fragment(acc2[i][j], 0.f);

    for (int kc = 0; kc < 2; ++kc) {
        for (int i = tid; i < 2048; i += NTHR) {
            int nn = i >> 4, k8 = i & 15;
            long src = ((long)(l * D + nn)) * TWOD + kc * 128 + k8 * 8;
            *(uint4*)(sW + nn * LDWF + k8 * 8) = *(const uint4*)(g_w2t + src);
        }
        __syncthreads();

        const __half* sTk = (kc == 0) ? sT0 : sA;
#pragma unroll
        for (int ks = 0; ks < 8; ++ks) {
            wmma::fragment<wmma::matrix_a, 16, 16, 16, __half, wmma::row_major> af[2];
            wmma::fragment<wmma::matrix_b, 16, 16, 16, __half, wmma::col_major> bf[2];
#pragma unroll
            for (int i = 0; i < 2; ++i)
                wmma::load_matrix_sync(af[i], sTk + (wr * 32 + i * 16) * LDTH + ks * 16, LDTH);
#pragma unroll
            for (int j = 0; j < 2; ++j)
                wmma::load_matrix_sync(bf[j], sW + (wc * 32 + j * 16) * LDWF + ks * 16, LDWF);
#pragma unroll
            for (int i = 0; i < 2; ++i)
#pragma unroll
                for (int j = 0; j < 2; ++j)
                    wmma::mma_sync(acc2[i][j], af[i], bf[j], acc2[i][j]);
        }
        __syncthreads();   // W2 slice reads done before overwrite / scratch use
    }

    // ---- epilogue: acc2 -> scratch -> bias -> gmem ----
#pragma unroll
    for (int i = 0; i < 2; ++i)
#pragma unroll
        for (int j = 0; j < 2; ++j)
            wmma::store_matrix_sync(scr + (i * 16) * LDS_SCR + j * 16,
                                    acc2[i][j], LDS_SCR, wmma::mem_row_major);
    __syncwarp();
    {
        int c = wc * 32 + lane;
        float bb = sb2[c];
        float cv = sc[c];
#pragma unroll
        for (int rr = 0; rr < 32; ++rr) {
            long grow = (long)row0 + wr * 32 + rr;
            if (grow >= n) continue;
            float o = scr[rr * LDS_SCR + lane] + bb;
            long off = grow * D + c;
            if (last) {
                out[off] = o;
            } else {
                float hv = fmaxf(o, 0.f);
                g_h[off]   = hv;
                g_agg[off] = hv + cv;
            }
        }
    }
}

// ---------------------------------------------------------------------------
extern "C" void kernel_launch(void* const* d_in, const int* in_sizes, int n_in,
                              void* d_out, int out_size) {
    const int*   x   = (const int*)d_in[0];
    const int*   ei  = (const int*)d_in[1];
    const int*   ea  = (const int*)d_in[2];
    const float* xe1 = (const float*)d_in[3];
    const float* xe2 = (const float*)d_in[4];
    const float* ee1 = (const float*)d_in[5];
    const float* ee2 = (const float*)d_in[6];
    const float* ee3 = (const float*)d_in[7];
    const float* W1  = (const float*)d_in[8];
    const float* b1  = (const float*)d_in[9];
    const float* W2  = (const float*)d_in[10];
    const float* b2  = (const float*)d_in[11];
    float* out = (float*)d_out;
    int n = in_sizes[0] / 2;   // x is [N,2]
    int e = in_sizes[1] / 2;   // edge_index is [2,E]

    cudaFuncSetAttribute(mlp_wmma_kernel,
                         cudaFuncAttributeMaxDynamicSharedMemorySize, SMEM_BYTES);

    prep_w<<<(NLAYER * TWOD * D + 255) / 256, 256>>>(W1, W2);
    embed_kernel<<<(n * (D / 4) + 255) / 256, 256>>>(x, xe1, xe2, ee1, ee2, ee3, n);

    int ntiles = (n + TILE_M - 1) / TILE_M;
    for (int l = 0; l < NLAYER; ++l) {
        scatter_kernel<<<2368, 256>>>(ei, ea,
                                      ee1 + (long)l * 7 * D,
                                      ee2 + (long)l * 3 * D,
                                      ee3 + (long)l * 3 * D, e);
        int last = (l == NLAYER - 1);
        mlp_wmma_kernel<<<ntiles, NTHR, SMEM_BYTES>>>(
            l, last, b1, b2, ee1, ee2, ee3, out, n);
    }
}

// round 15
// speedup vs baseline: 2.2381x; 1.0159x over previous
#include <cuda_runtime.h>
#include <cuda_fp16.h>
#include <mma.h>

using namespace nvcuda;

#define D      128
#define TWOD   256
#define MAXN   200000
#define NLAYER 5
#define TILE_M 96
#define NTHR   384

// ---------------- device scratch (allocation-free rule) ----------------
__device__ float g_h[(long)MAXN * D];
__device__ float g_agg[(long)MAXN * D];
// pre-transposed fp16 weights: w1t[l][n][k] = W1[l][k][n], w2t[l][n][k] = W2[l][k][n]
__device__ __half g_w1t[NLAYER * TWOD * D];
__device__ __half g_w2t[NLAYER * D * TWOD];

// ---------------- smem byte layout (total 109568 -> 2 CTAs/SM, 24 warps) ----
// R0: sA fp16 [96][136] = 26112 ; reused as T1 after phase1 h1
// R1: T0 fp16 [96][136] = 26112
// R2: W slice fp16 [128][136] = 34816 ; per-warp fp32 scratch (12*4608=55296)
//     aliases W + padding up to OFF_SB1
#define OFF_A   0
#define OFF_T0  26112
#define OFF_W   52224
#define OFF_SB1 107520
#define OFF_SB2 108544
#define OFF_SC  109056
#define SMEM_BYTES 109568

#define LDA  136
#define LDTH 136
#define LDWF 136
#define LDS_SCR 36      /* per-warp scratch ldm (fp32) */
#define SCR_STRIDE 4608 /* 32*36*4 bytes per warp */

#define CP_ASYNC16(saddr, gptr) \
    asm volatile("cp.async.cg.shared.global [%0], [%1], 16;" \
                 :: "r"(saddr), "l"(gptr))
#define CP_ASYNC_WAIT_ALL() do { \
    asm volatile("cp.async.commit_group;"); \
    asm volatile("cp.async.wait_group 0;" ::: "memory"); \
} while (0)

__device__ __forceinline__ float4 f4add(float4 a, float4 b) {
    return make_float4(a.x + b.x, a.y + b.y, a.z + b.z, a.w + b.w);
}

// ---------------------------------------------------------------------------
// prep: transpose weights to [n][k] fp16 once
// ---------------------------------------------------------------------------
__global__ void prep_w(const float* __restrict__ W1, const float* __restrict__ W2) {
    int i = blockIdx.x * blockDim.x + threadIdx.x;
    int tot = NLAYER * TWOD * D;
    if (i >= tot) return;
    {   // w1t[l][n][k] = W1[l][k][n]
        int l = i / (TWOD * D), rem = i % (TWOD * D);
        int nn = rem / D, kk = rem % D;
        g_w1t[i] = __float2half_rn(W1[(l * D + kk) * TWOD + nn]);
    }
    {   // w2t[l][n][k] = W2[l][k][n]
        int l = i / (D * TWOD), rem = i % (D * TWOD);
        int nn = rem / TWOD, kk = rem % TWOD;
        g_w2t[i] = __float2half_rn(W2[(l * TWOD + kk) * D + nn]);
    }
}

// ---------------------------------------------------------------------------
// embed: h = xe1[x0] + xe2[x1] ; agg = h + selfloop_const(layer 0)
// ---------------------------------------------------------------------------
__global__ void embed_kernel(const int* __restrict__ x,
                             const float* __restrict__ xe1,
                             const float* __restrict__ xe2,
                             const float* __restrict__ ee1,
                             const float* __restrict__ ee2,
                             const float* __restrict__ ee3,
                             int n) {
    int idx = blockIdx.x * blockDim.x + threadIdx.x;
    if (idx >= n * (D / 4)) return;
    int node = idx >> 5;
    int j    = idx & 31;
    int a = x[node * 2 + 0];
    int c = x[node * 2 + 1];
    float4 h = f4add(((const float4*)xe1)[a * 32 + j],
                     ((const float4*)xe2)[c * 32 + j]);
    float4 cv = f4add(f4add(((const float4*)(ee1 + 4 * D))[j],
                            ((const float4*)ee2)[j]),
                      ((const float4*)ee3)[j]);
    ((float4*)g_h)[idx]   = h;
    ((float4*)g_agg)[idx] = f4add(h, cv);
}

// ---------------------------------------------------------------------------
// scatter: agg[col[e]] += h[row[e]] + edge_emb(e)   (warp/edge, red.add.v4)
// ---------------------------------------------------------------------------
__global__ void scatter_kernel(const int* __restrict__ ei,
                               const int* __restrict__ ea,
                               const float* __restrict__ e1,
                               const float* __restrict__ e2,
                               const float* __restrict__ e3,
                               int e) {
    __shared__ float s1[7 * D], s2[3 * D], s3[3 * D];
    for (int i = threadIdx.x; i < 7 * D; i += blockDim.x) s1[i] = e1[i];
    for (int i = threadIdx.x; i < 3 * D; i += blockDim.x) s2[i] = e2[i];
    for (int i = threadIdx.x; i < 3 * D; i += blockDim.x) s3[i] = e3[i];
    __syncthreads();

    int lane  = threadIdx.x & 31;
    int warp  = (blockIdx.x * blockDim.x + threadIdx.x) >> 5;
    int nwarp = (gridDim.x * blockDim.x) >> 5;

    for (int ed = warp; ed < e; ed += nwarp) {
        int row = ei[ed];
        int col = ei[e + ed];
        int bt  = ea[ed * 3 + 0];
        int bd  = ea[ed * 3 + 1];
        int bb  = ea[ed * 3 + 2];
        float4 emb = f4add(f4add(*(const float4*)&s1[bt * D + lane * 4],
                                 *(const float4*)&s2[bd * D + lane * 4]),
                           *(const float4*)&s3[bb * D + lane * 4]);
        float4 hv = *(const float4*)(g_h + (long)row * D + lane * 4);
        float4 m  = f4add(emb, hv);
        float* p  = g_agg + (long)col * D + lane * 4;
        asm volatile("red.global.add.v4.f32 [%0], {%1,%2,%3,%4};"
                     :: "l"(p), "f"(m.x), "f"(m.y), "f"(m.z), "f"(m.w)
                     : "memory");
    }
}

// ---------------------------------------------------------------------------
// wmma fused GIN MLP v6: 96-row tile, 12 warps, cp.async W loads
// ---------------------------------------------------------------------------
__global__ void __launch_bounds__(NTHR, 2)
mlp_wmma_kernel(int l, int last,
                const float* __restrict__ b1g, const float* __restrict__ b2g,
                const float* __restrict__ ee1, const float* __restrict__ ee2,
                const float* __restrict__ ee3,
                float* __restrict__ out, int n) {
    extern __shared__ char smem[];
    __half* sA = (__half*)(smem + OFF_A);     // A tile; becomes T1 after phase1 h1
    __half* sT0 = (__half*)(smem + OFF_T0);
    __half* sW = (__half*)(smem + OFF_W);
    float* sb1 = (float*)(smem + OFF_SB1);
    float* sb2 = (float*)(smem + OFF_SB2);
    float* sc  = (float*)(smem + OFF_SC);

    int tid  = threadIdx.x;
    int wid  = tid >> 5;
    int lane = tid & 31;
    int wr = wid >> 2, wc = wid & 3;   // 3x4 warp grid, 32x32 warp tiles
    int row0 = blockIdx.x * TILE_M;
    float* scr = (float*)(smem + OFF_W + wid * SCR_STRIDE);  // per-warp 32x36 fp32
    unsigned sW_u32 = (unsigned)__cvta_generic_to_shared(sW);

    // biases + next-layer self-loop const
    for (int i = tid; i < TWOD; i += NTHR) sb1[i] = b1g[l * TWOD + i];
    if (tid < D) {
        sb2[tid] = b2g[l * D + tid];
        float cv = 0.f;
        if (!last) {
            int ln = l + 1;
            cv = ee1[(ln * 7 + 4) * D + tid] + ee2[ln * 3 * D + tid]
               + ee3[ln * 3 * D + tid];
        }
        sc[tid] = cv;
    }

    // ---- load A tile fp32 -> fp16 smem ----
    for (int i = tid; i < TILE_M * (D / 4); i += NTHR) {  // 3072
        int r = i / 32, c4 = i & 31;
        float4 v = make_float4(0.f, 0.f, 0.f, 0.f);
        if (row0 + r < n)
            v = *(const float4*)(g_agg + ((long)(row0 + r)) * D + c4 * 4);
        __half2 p0 = __floats2half2_rn(v.x, v.y);
        __half2 p1 = __floats2half2_rn(v.z, v.w);
        *(__half2*)(sA + r * LDA + c4 * 4)     = p0;
        *(__half2*)(sA + r * LDA + c4 * 4 + 2) = p1;
    }

    // ================= PHASE 1: T = relu(A @ W1 + b1), half by half =========
    for (int h = 0; h < 2; ++h) {
        // load W1 half-slice [128n][128k] via cp.async
        for (int i = tid; i < 2048; i += NTHR) {
            int nn = i >> 4, k8 = i & 15;
            long src = ((long)(l * TWOD + h * 128 + nn)) * D + k8 * 8;
            CP_ASYNC16(sW_u32 + (nn * LDWF + k8 * 8) * 2, g_w1t + src);
        }
        CP_ASYNC_WAIT_ALL();
        __syncthreads();   // W (+A on first iter) visible

        wmma::fragment<wmma::accumulator, 16, 16, 16, float> acc1[2][2];
#pragma unroll
        for (int i = 0; i < 2; ++i)
#pragma unroll
            for (int j = 0; j < 2; ++j) wmma::fill_fragment(acc1[i][j], 0.f);

#pragma unroll
        for (int ks = 0; ks < 8; ++ks) {
            wmma::fragment<wmma::matrix_a, 16, 16, 16, __half, wmma::row_major> af[2];
            wmma::fragment<wmma::matrix_b, 16, 16, 16, __half, wmma::col_major> bf[2];
#pragma unroll
            for (int i = 0; i < 2; ++i)
                wmma::load_matrix_sync(af[i], sA + (wr * 32 + i * 16) * LDA + ks * 16, LDA);
#pragma unroll
            for (int j = 0; j < 2; ++j)
                wmma::load_matrix_sync(bf[j], sW + (wc * 32 + j * 16) * LDWF + ks * 16, LDWF);
#pragma unroll
            for (int i = 0; i < 2; ++i)
#pragma unroll
                for (int j = 0; j < 2; ++j)
                    wmma::mma_sync(acc1[i][j], af[i], bf[j], acc1[i][j]);
        }

        __syncthreads();   // all W1h (and, for h=1, all sA) reads done

        // acc1 -> per-warp scratch (aliases W region) -> relu+bias -> T half
        __half* sTd = (h == 0) ? sT0 : sA;   // T1 aliases sA (sA dead after h1 MMAs)
#pragma unroll
        for (int i = 0; i < 2; ++i)
#pragma unroll
            for (int j = 0; j < 2; ++j)
                wmma::store_matrix_sync(scr + (i * 16) * LDS_SCR + j * 16,
                                        acc1[i][j], LDS_SCR, wmma::mem_row_major);
        __syncwarp();
        {
            float bb = sb1[h * 128 + wc * 32 + lane];
#pragma unroll
            for (int rr = 0; rr < 32; ++rr) {
                float t = fmaxf(scr[rr * LDS_SCR + lane] + bb, 0.f);
                sTd[(wr * 32 + rr) * LDTH + wc * 32 + lane] = __float2half_rn(t);
            }
        }
        __syncthreads();   // scratch reads + T writes done before next W load
    }

    // ================= PHASE 2: C2 = T @ W2, k-slice by k-slice =============
    wmma::fragment<wmma::accumulator, 16, 16, 16, float> acc2[2][2];
#pragma unroll
    for (int i = 0; i < 2; ++i)
#pragma unroll
        for (int j = 0; j < 2; ++j) wmma::fill_fragment(acc2[i][j], 0.f);

    for (int kc = 0; kc < 2; ++kc) {
        for (int i = tid; i < 2048; i += NTHR) {
            int nn = i >> 4, k8 = i & 15;
            long src = ((long)(l * D + nn)) * TWOD + kc * 128 + k8 * 8;
            CP_ASYNC16(sW_u32 + (nn * LDWF + k8 * 8) * 2, g_w2t + src);
        }
        CP_ASYNC_WAIT_ALL();
        __syncthreads();

        const __half* sTk = (kc == 0) ? sT0 : sA;
#pragma unroll
        for (int ks = 0; ks < 8; ++ks) {
            wmma::fragment<wmma::matrix_a, 16, 16, 16, __half, wmma::row_major> af[2];
            wmma::fragment<wmma::matrix_b, 16, 16, 16, __half, wmma::col_major> bf[2];
#pragma unroll
            for (int i = 0; i < 2; ++i)
                wmma::load_matrix_sync(af[i], sTk + (wr * 32 + i * 16) * LDTH + ks * 16, LDTH);
#pragma unroll
            for (int j = 0; j < 2; ++j)
                wmma::load_matrix_sync(bf[j], sW + (wc * 32 + j * 16) * LDWF + ks * 16, LDWF);
#pragma unroll
            for (int i = 0; i < 2; ++i)
#pragma unroll
                for (int j = 0; j < 2; ++j)
                    wmma::mma_sync(acc2[i][j], af[i], bf[j], acc2[i][j]);
        }
        __syncthreads();   // W2 slice reads done before overwrite / scratch use
    }

    // ---- epilogue: acc2 -> scratch -> bias -> gmem ----
#pragma unroll
    for (int i = 0; i < 2; ++i)
#pragma unroll
        for (int j = 0; j < 2; ++j)
            wmma::store_matrix_sync(scr + (i * 16) * LDS_SCR + j * 16,
                                    acc2[i][j], LDS_SCR, wmma::mem_row_major);
    __syncwarp();
    {
        int c = wc * 32 + lane;
        float bb = sb2[c];
        float cv = sc[c];
#pragma unroll
        for (int rr = 0; rr < 32; ++rr) {
            long grow = (long)row0 + wr * 32 + rr;
            if (grow >= n) continue;
            float o = scr[rr * LDS_SCR + lane] + bb;
            long off = grow * D + c;
            if (last) {
                out[off] = o;
            } else {
                float hv = fmaxf(o, 0.f);
                g_h[off]   = hv;
                g_agg[off] = hv + cv;
            }
        }
    }
}

// ---------------------------------------------------------------------------
extern "C" void kernel_launch(void* const* d_in, const int* in_sizes, int n_in,
                              void* d_out, int out_size) {
    const int*   x   = (const int*)d_in[0];
    const int*   ei  = (const int*)d_in[1];
    const int*   ea  = (const int*)d_in[2];
    const float* xe1 = (const float*)d_in[3];
    const float* xe2 = (const float*)d_in[4];
    const float* ee1 = (const float*)d_in[5];
    const float* ee2 = (const float*)d_in[6];
    const float* ee3 = (const float*)d_in[7];
    const float* W1  = (const float*)d_in[8];
    const float* b1  = (const float*)d_in[9];
    const float* W2  = (const float*)d_in[10];
    const float* b2  = (const float*)d_in[11];
    float* out = (float*)d_out;
    int n = in_sizes[0] / 2;   // x is [N,2]
    int e = in_sizes[1] / 2;   // edge_index is [2,E]

    cudaFuncSetAttribute(mlp_wmma_kernel,
                         cudaFuncAttributeMaxDynamicSharedMemorySize, SMEM_BYTES);

    prep_w<<<(NLAYER * TWOD * D + 255) / 256, 256>>>(W1, W2);
    embed_kernel<<<(n * (D / 4) + 255) / 256, 256>>>(x, xe1, xe2, ee1, ee2, ee3, n);

    int ntiles = (n + TILE_M - 1) / TILE_M;
    for (int l = 0; l < NLAYER; ++l) {
        scatter_kernel<<<2368, 256>>>(ei, ea,
                                      ee1 + (long)l * 7 * D,
                                      ee2 + (long)l * 3 * D,
                                      ee3 + (long)l * 3 * D, e);
        int last = (l == NLAYER - 1);
        mlp_wmma_kernel<<<ntiles, NTHR, SMEM_BYTES>>>(
            l, last, b1, b2, ee1, ee2, ee3, out, n);
    }
}

// round 16
// speedup vs baseline: 2.4321x; 1.0867x over previous
#include <cuda_runtime.h>
#include <cuda_fp16.h>
#include <mma.h>

using namespace nvcuda;

#define D      128
#define TWOD   256
#define MAXN   200000
#define NLAYER 5
#define TILE_M 96
#define NTHR   384

// ---------------- device scratch (allocation-free rule) ----------------
__device__ __half g_h16[(long)MAXN * D];     // h stored fp16 (scatter gather)
__device__ float  g_agg[(long)MAXN * D];
// pre-transposed fp16 weights: w1t[l][n][k] = W1[l][k][n], w2t[l][n][k] = W2[l][k][n]
__device__ __half g_w1t[NLAYER * TWOD * D];
__device__ __half g_w2t[NLAYER * D * TWOD];

// ---------------- smem byte layout (total 109568 -> 2 CTAs/SM, 24 warps) ----
#define OFF_A   0
#define OFF_T0  26112
#define OFF_W   52224
#define OFF_SB1 107520
#define OFF_SB2 108544
#define OFF_SC  109056
#define SMEM_BYTES 109568

#define LDA  136
#define LDTH 136
#define LDWF 136
#define LDS_SCR 36      /* per-warp scratch ldm (fp32) */
#define SCR_STRIDE 4608 /* 32*36*4 bytes per warp */

#define CP_ASYNC16(saddr, gptr) \
    asm volatile("cp.async.cg.shared.global [%0], [%1], 16;" \
                 :: "r"(saddr), "l"(gptr))
#define CP_ASYNC_WAIT_ALL() do { \
    asm volatile("cp.async.commit_group;"); \
    asm volatile("cp.async.wait_group 0;" ::: "memory"); \
} while (0)

__device__ __forceinline__ float4 f4add(float4 a, float4 b) {
    return make_float4(a.x + b.x, a.y + b.y, a.z + b.z, a.w + b.w);
}

// ---------------------------------------------------------------------------
// prep: transpose weights to [n][k] fp16 once
// ---------------------------------------------------------------------------
__global__ void prep_w(const float* __restrict__ W1, const float* __restrict__ W2) {
    int i = blockIdx.x * blockDim.x + threadIdx.x;
    int tot = NLAYER * TWOD * D;
    if (i >= tot) return;
    {   // w1t[l][n][k] = W1[l][k][n]
        int l = i / (TWOD * D), rem = i % (TWOD * D);
        int nn = rem / D, kk = rem % D;
        g_w1t[i] = __float2half_rn(W1[(l * D + kk) * TWOD + nn]);
    }
    {   // w2t[l][n][k] = W2[l][k][n]
        int l = i / (D * TWOD), rem = i % (D * TWOD);
        int nn = rem / TWOD, kk = rem % TWOD;
        g_w2t[i] = __float2half_rn(W2[(l * TWOD + kk) * D + nn]);
    }
}

// ---------------------------------------------------------------------------
// embed: h = xe1[x0] + xe2[x1] (fp16 store) ; agg = h + selfloop_const(l=0)
// ---------------------------------------------------------------------------
__global__ void embed_kernel(const int* __restrict__ x,
                             const float* __restrict__ xe1,
                             const float* __restrict__ xe2,
                             const float* __restrict__ ee1,
                             const float* __restrict__ ee2,
                             const float* __restrict__ ee3,
                             int n) {
    int idx = blockIdx.x * blockDim.x + threadIdx.x;
    if (idx >= n * (D / 4)) return;
    int node = idx >> 5;
    int j    = idx & 31;
    int a = x[node * 2 + 0];
    int c = x[node * 2 + 1];
    float4 h = f4add(((const float4*)xe1)[a * 32 + j],
                     ((const float4*)xe2)[c * 32 + j]);
    float4 cv = f4add(f4add(((const float4*)(ee1 + 4 * D))[j],
                            ((const float4*)ee2)[j]),
                      ((const float4*)ee3)[j]);
    __half2 p0 = __floats2half2_rn(h.x, h.y);
    __half2 p1 = __floats2half2_rn(h.z, h.w);
    *(__half2*)(g_h16 + (long)idx * 4)     = p0;
    *(__half2*)(g_h16 + (long)idx * 4 + 2) = p1;
    ((float4*)g_agg)[idx] = f4add(h, cv);
}

// ---------------------------------------------------------------------------
// scatter: agg[col[e]] += h16[row[e]] + edge_emb(e)   (warp/edge, red.add.v4)
// gather is fp16 -> 256B/edge instead of 512B
// ---------------------------------------------------------------------------
__global__ void scatter_kernel(const int* __restrict__ ei,
                               const int* __restrict__ ea,
                               const float* __restrict__ e1,
                               const float* __restrict__ e2,
                               const float* __restrict__ e3,
                               int e) {
    __shared__ float s1[7 * D], s2[3 * D], s3[3 * D];
    for (int i = threadIdx.x; i < 7 * D; i += blockDim.x) s1[i] = e1[i];
    for (int i = threadIdx.x; i < 3 * D; i += blockDim.x) s2[i] = e2[i];
    for (int i = threadIdx.x; i < 3 * D; i += blockDim.x) s3[i] = e3[i];
    __syncthreads();

    int lane  = threadIdx.x & 31;
    int warp  = (blockIdx.x * blockDim.x + threadIdx.x) >> 5;
    int nwarp = (gridDim.x * blockDim.x) >> 5;

    for (int ed = warp; ed < e; ed += nwarp) {
        int row = ei[ed];
        int col = ei[e + ed];
        int bt  = ea[ed * 3 + 0];
        int bd  = ea[ed * 3 + 1];
        int bb  = ea[ed * 3 + 2];
        float4 emb = f4add(f4add(*(const float4*)&s1[bt * D + lane * 4],
                                 *(const float4*)&s2[bd * D + lane * 4]),
                           *(const float4*)&s3[bb * D + lane * 4]);
        // fp16 gather: 4 halves per lane (8B)
        uint2 raw = *(const uint2*)(g_h16 + (long)row * D + lane * 4);
        float2 f01 = __half22float2(*(__half2*)&raw.x);
        float2 f23 = __half22float2(*(__half2*)&raw.y);
        float4 m;
        m.x = emb.x + f01.x;
        m.y = emb.y + f01.y;
        m.z = emb.z + f23.x;
        m.w = emb.w + f23.y;
        float* p = g_agg + (long)col * D + lane * 4;
        asm volatile("red.global.add.v4.f32 [%0], {%1,%2,%3,%4};"
                     :: "l"(p), "f"(m.x), "f"(m.y), "f"(m.z), "f"(m.w)
                     : "memory");
    }
}

// ---------------------------------------------------------------------------
// wmma fused GIN MLP v6: 96-row tile, 12 warps, cp.async W loads
// ---------------------------------------------------------------------------
__global__ void __launch_bounds__(NTHR, 2)
mlp_wmma_kernel(int l, int last,
                const float* __restrict__ b1g, const float* __restrict__ b2g,
                const float* __restrict__ ee1, const float* __restrict__ ee2,
                const float* __restrict__ ee3,
                float* __restrict__ out, int n) {
    extern __shared__ char smem[];
    __half* sA = (__half*)(smem + OFF_A);     // A tile; becomes T1 after phase1 h1
    __half* sT0 = (__half*)(smem + OFF_T0);
    __half* sW = (__half*)(smem + OFF_W);
    float* sb1 = (float*)(smem + OFF_SB1);
    float* sb2 = (float*)(smem + OFF_SB2);
    float* sc  = (float*)(smem + OFF_SC);

    int tid  = threadIdx.x;
    int wid  = tid >> 5;
    int lane = tid & 31;
    int wr = wid >> 2, wc = wid & 3;   // 3x4 warp grid, 32x32 warp tiles
    int row0 = blockIdx.x * TILE_M;
    float* scr = (float*)(smem + OFF_W + wid * SCR_STRIDE);  // per-warp 32x36 fp32
    unsigned sW_u32 = (unsigned)__cvta_generic_to_shared(sW);

    // biases + next-layer self-loop const
    for (int i = tid; i < TWOD; i += NTHR) sb1[i] = b1g[l * TWOD + i];
    if (tid < D) {
        sb2[tid] = b2g[l * D + tid];
        float cv = 0.f;
        if (!last) {
            int ln = l + 1;
            cv = ee1[(ln * 7 + 4) * D + tid] + ee2[ln * 3 * D + tid]
               + ee3[ln * 3 * D + tid];
        }
        sc[tid] = cv;
    }

    // ---- load A tile fp32 -> fp16 smem ----
    for (int i = tid; i < TILE_M * (D / 4); i += NTHR) {  // 3072
        int r = i / 32, c4 = i & 31;
        float4 v = make_float4(0.f, 0.f, 0.f, 0.f);
        if (row0 + r < n)
            v = *(const float4*)(g_agg + ((long)(row0 + r)) * D + c4 * 4);
        __half2 p0 = __floats2half2_rn(v.x, v.y);
        __half2 p1 = __floats2half2_rn(v.z, v.w);
        *(__half2*)(sA + r * LDA + c4 * 4)     = p0;
        *(__half2*)(sA + r * LDA + c4 * 4 + 2) = p1;
    }

    // ================= PHASE 1: T = relu(A @ W1 + b1), half by half =========
    for (int h = 0; h < 2; ++h) {
        // load W1 half-slice [128n][128k] via cp.async
        for (int i = tid; i < 2048; i += NTHR) {
            int nn = i >> 4, k8 = i & 15;
            long src = ((long)(l * TWOD + h * 128 + nn)) * D + k8 * 8;
            CP_ASYNC16(sW_u32 + (nn * LDWF + k8 * 8) * 2, g_w1t + src);
        }
        CP_ASYNC_WAIT_ALL();
        __syncthreads();   // W (+A on first iter) visible

        wmma::fragment<wmma::accumulator, 16, 16, 16, float> acc1[2][2];
#pragma unroll
        for (int i = 0; i < 2; ++i)
#pragma unroll
            for (int j = 0; j < 2; ++j) wmma::fill_fragment(acc1[i][j], 0.f);

#pragma unroll
        for (int ks = 0; ks < 8; ++ks) {
            wmma::fragment<wmma::matrix_a, 16, 16, 16, __half, wmma::row_major> af[2];
            wmma::fragment<wmma::matrix_b, 16, 16, 16, __half, wmma::col_major> bf[2];
#pragma unroll
            for (int i = 0; i < 2; ++i)
                wmma::load_matrix_sync(af[i], sA + (wr * 32 + i * 16) * LDA + ks * 16, LDA);
#pragma unroll
            for (int j = 0; j < 2; ++j)
                wmma::load_matrix_sync(bf[j], sW + (wc * 32 + j * 16) * LDWF + ks * 16, LDWF);
#pragma unroll
            for (int i = 0; i < 2; ++i)
#pragma unroll
                for (int j = 0; j < 2; ++j)
                    wmma::mma_sync(acc1[i][j], af[i], bf[j], acc1[i][j]);
        }

        __syncthreads();   // all W1h (and, for h=1, all sA) reads done

        // acc1 -> per-warp scratch (aliases W region) -> relu+bias -> T half
        __half* sTd = (h == 0) ? sT0 : sA;   // T1 aliases sA (sA dead after h1 MMAs)
#pragma unroll
        for (int i = 0; i < 2; ++i)
#pragma unroll
            for (int j = 0; j < 2; ++j)
                wmma::store_matrix_sync(scr + (i * 16) * LDS_SCR + j * 16,
                                        acc1[i][j], LDS_SCR, wmma::mem_row_major);
        __syncwarp();
        {
            float bb = sb1[h * 128 + wc * 32 + lane];
#pragma unroll
            for (int rr = 0; rr < 32; ++rr) {
                float t = fmaxf(scr[rr * LDS_SCR + lane] + bb, 0.f);
                sTd[(wr * 32 + rr) * LDTH + wc * 32 + lane] = __float2half_rn(t);
            }
        }
        __syncthreads();   // scratch reads + T writes done before next W load
    }

    // ================= PHASE 2: C2 = T @ W2, k-slice by k-slice =============
    wmma::fragment<wmma::accumulator, 16, 16, 16, float> acc2[2][2];
#pragma unroll
    for (int i = 0; i < 2; ++i)
#pragma unroll
        for (int j = 0; j < 2; ++j) wmma::fill_fragment(acc2[i][j], 0.f);

    for (int kc = 0; kc < 2; ++kc) {
        for (int i = tid; i < 2048; i += NTHR) {
            int nn = i >> 4, k8 = i & 15;
            long src = ((long)(l * D + nn)) * TWOD + kc * 128 + k8 * 8;
            CP_ASYNC16(sW_u32 + (nn * LDWF + k8 * 8) * 2, g_w2t + src);
        }
        CP_ASYNC_WAIT_ALL();
        __syncthreads();

        const __half* sTk = (kc == 0) ? sT0 : sA;
#pragma unroll
        for (int ks = 0; ks < 8; ++ks) {
            wmma::fragment<wmma::matrix_a, 16, 16, 16, __half, wmma::row_major> af[2];
            wmma::fragment<wmma::matrix_b, 16, 16, 16, __half, wmma::col_major> bf[2];
#pragma unroll
            for (int i = 0; i < 2; ++i)
                wmma::load_matrix_sync(af[i], sTk + (wr * 32 + i * 16) * LDTH + ks * 16, LDTH);
#pragma unroll
            for (int j = 0; j < 2; ++j)
                wmma::load_matrix_sync(bf[j], sW + (wc * 32 + j * 16) * LDWF + ks * 16, LDWF);
#pragma unroll
            for (int i = 0; i < 2; ++i)
#pragma unroll
                for (int j = 0; j < 2; ++j)
                    wmma::mma_sync(acc2[i][j], af[i], bf[j], acc2[i][j]);
        }
        __syncthreads();   // W2 slice reads done before overwrite / scratch use
    }

    // ---- epilogue: acc2 -> scratch -> bias -> gmem ----
#pragma unroll
    for (int i = 0; i < 2; ++i)
#pragma unroll
        for (int j = 0; j < 2; ++j)
            wmma::store_matrix_sync(scr + (i * 16) * LDS_SCR + j * 16,
                                    acc2[i][j], LDS_SCR, wmma::mem_row_major);
    __syncwarp();
    {
        int c = wc * 32 + lane;
        float bb = sb2[c];
        float cv = sc[c];
#pragma unroll
        for (int rr = 0; rr < 32; ++rr) {
            long grow = (long)row0 + wr * 32 + rr;
            if (grow >= n) continue;
            float o = scr[rr * LDS_SCR + lane] + bb;
            long off = grow * D + c;
            if (last) {
                out[off] = o;
            } else {
                float hv = fmaxf(o, 0.f);
                g_h16[off] = __float2half_rn(hv);   // fp16 h for scatter gather
                g_agg[off] = hv + cv;               // self term stays fp32
            }
        }
    }
}

// ---------------------------------------------------------------------------
extern "C" void kernel_launch(void* const* d_in, const int* in_sizes, int n_in,
                              void* d_out, int out_size) {
    const int*   x   = (const int*)d_in[0];
    const int*   ei  = (const int*)d_in[1];
    const int*   ea  = (const int*)d_in[2];
    const float* xe1 = (const float*)d_in[3];
    const float* xe2 = (const float*)d_in[4];
    const float* ee1 = (const float*)d_in[5];
    const float* ee2 = (const float*)d_in[6];
    const float* ee3 = (const float*)d_in[7];
    const float* W1  = (const float*)d_in[8];
    const float* b1  = (const float*)d_in[9];
    const float* W2  = (const float*)d_in[10];
    const float* b2  = (const float*)d_in[11];
    float* out = (float*)d_out;
    int n = in_sizes[0] / 2;   // x is [N,2]
    int e = in_sizes[1] / 2;   // edge_index is [2,E]

    cudaFuncSetAttribute(mlp_wmma_kernel,
                         cudaFuncAttributeMaxDynamicSharedMemorySize, SMEM_BYTES);

    prep_w<<<(NLAYER * TWOD * D + 255) / 256, 256>>>(W1, W2);
    embed_kernel<<<(n * (D / 4) + 255) / 256, 256>>>(x, xe1, xe2, ee1, ee2, ee3, n);

    int ntiles = (n + TILE_M - 1) / TILE_M;
    for (int l = 0; l < NLAYER; ++l) {
        scatter_kernel<<<2368, 256>>>(ei, ea,
                                      ee1 + (long)l * 7 * D,
                                      ee2 + (long)l * 3 * D,
                                      ee3 + (long)l * 3 * D, e);
        int last = (l == NLAYER - 1);
        mlp_wmma_kernel<<<ntiles, NTHR, SMEM_BYTES>>>(
            l, last, b1, b2, ee1, ee2, ee3, out, n);
    }
}

// round 17
// speedup vs baseline: 2.8889x; 1.1878x over previous
#include <cuda_runtime.h>
#include <cuda_fp16.h>

#define D      128
#define TWOD   256
#define MAXN   200000
#define NLAYER 5
#define TILE_M 96
#define NTHR   384

// ---------------- device scratch (allocation-free rule) ----------------
__device__ __half g_h16[(long)MAXN * D];     // h stored fp16 (scatter gather)
__device__ float  g_agg[(long)MAXN * D];
// pre-transposed fp16 weights: w1t[l][n][k] = W1[l][k][n], w2t[l][n][k] = W2[l][k][n]
__device__ __half g_w1t[NLAYER * TWOD * D];
__device__ __half g_w2t[NLAYER * D * TWOD];

// ---------------- smem byte layout (total 89088 -> 2 CTAs/SM, 24 warps) -----
// R0: sA fp16 [96][136] = 26112 ; reused as T1 after phase1 h1
// R1: T0 fp16 [96][136] = 26112
// R2: W slice fp16 [128][136] = 34816  (no fp32 scratch needed anymore)
#define OFF_A   0
#define OFF_T0  26112
#define OFF_W   52224
#define OFF_SB1 87040
#define OFF_SB2 88064
#define OFF_SC  88576
#define SMEM_BYTES 89088

#define LDA  136      /* halves; 272B row stride for A and T tiles */
#define LDWF 136

#define CP_ASYNC16(saddr, gptr) \
    asm volatile("cp.async.cg.shared.global [%0], [%1], 16;" \
                 :: "r"(saddr), "l"(gptr))
#define CP_ASYNC_WAIT_ALL() do { \
    asm volatile("cp.async.commit_group;"); \
    asm volatile("cp.async.wait_group 0;" ::: "memory"); \
} while (0)

#define LDM_X4(R0, R1, R2, R3, ADDR) \
    asm volatile("ldmatrix.sync.aligned.m8n8.x4.shared.b16 {%0,%1,%2,%3}, [%4];" \
                 : "=r"(R0), "=r"(R1), "=r"(R2), "=r"(R3) : "r"(ADDR))

#define MMA_16816(Dd, Aa, B0, B1) \
    asm volatile("mma.sync.aligned.m16n8k16.row.col.f32.f16.f16.f32 " \
                 "{%0,%1,%2,%3}, {%4,%5,%6,%7}, {%8,%9}, {%10,%11,%12,%13};" \
                 : "=f"(Dd[0]), "=f"(Dd[1]), "=f"(Dd[2]), "=f"(Dd[3]) \
                 : "r"(Aa[0]), "r"(Aa[1]), "r"(Aa[2]), "r"(Aa[3]), \
                   "r"(B0), "r"(B1), \
                   "f"(Dd[0]), "f"(Dd[1]), "f"(Dd[2]), "f"(Dd[3]))

__device__ __forceinline__ float4 f4add(float4 a, float4 b) {
    return make_float4(a.x + b.x, a.y + b.y, a.z + b.z, a.w + b.w);
}

// warp GEMM: acc[2][4] (m16n8 tiles) += Atile[32x128] @ W[n 32x128k]^T
// aTile: smem addr of A tile row (wr*32), col 0 (ld = LDA halves)
// bBase0/1: per-lane ldmatrix addrs for n-chunk pairs p=0,1 at k=0
__device__ __forceinline__ void warp_gemm(float acc[2][4][4],
                                          unsigned aTile,
                                          unsigned bBase0, unsigned bBase1,
                                          int lane) {
    unsigned aOff = ((lane & 15) * LDA + (lane >> 4) * 8) * 2;
#pragma unroll
    for (int ks = 0; ks < 8; ++ks) {
        unsigned a0[4], a1[4], b0[4], b1[4];
        LDM_X4(a0[0], a0[1], a0[2], a0[3], aTile + aOff + ks * 32);
        LDM_X4(a1[0], a1[1], a1[2], a1[3], aTile + aOff + 16 * LDA * 2 + ks * 32);
        LDM_X4(b0[0], b0[1], b0[2], b0[3], bBase0 + ks * 32);
        LDM_X4(b1[0], b1[1], b1[2], b1[3], bBase1 + ks * 32);
        MMA_16816(acc[0][0], a0, b0[0], b0[1]);
        MMA_16816(acc[0][1], a0, b0[2], b0[3]);
        MMA_16816(acc[0][2], a0, b1[0], b1[1]);
        MMA_16816(acc[0][3], a0, b1[2], b1[3]);
        MMA_16816(acc[1][0], a1, b0[0], b0[1]);
        MMA_16816(acc[1][1], a1, b0[2], b0[3]);
        MMA_16816(acc[1][2], a1, b1[0], b1[1]);
        MMA_16816(acc[1][3], a1, b1[2], b1[3]);
    }
}

// ---------------------------------------------------------------------------
// prep: transpose weights to [n][k] fp16 once
// ---------------------------------------------------------------------------
__global__ void prep_w(const float* __restrict__ W1, const float* __restrict__ W2) {
    int i = blockIdx.x * blockDim.x + threadIdx.x;
    int tot = NLAYER * TWOD * D;
    if (i >= tot) return;
    {   // w1t[l][n][k] = W1[l][k][n]
        int l = i / (TWOD * D), rem = i % (TWOD * D);
        int nn = rem / D, kk = rem % D;
        g_w1t[i] = __float2half_rn(W1[(l * D + kk) * TWOD + nn]);
    }
    {   // w2t[l][n][k] = W2[l][k][n]
        int l = i / (D * TWOD), rem = i % (D * TWOD);
        int nn = rem / TWOD, kk = rem % TWOD;
        g_w2t[i] = __float2half_rn(W2[(l * TWOD + kk) * D + nn]);
    }
}

// ---------------------------------------------------------------------------
// embed: h = xe1[x0] + xe2[x1] (fp16 store) ; agg = h + selfloop_const(l=0)
// ---------------------------------------------------------------------------
__global__ void embed_kernel(const int* __restrict__ x,
                             const float* __restrict__ xe1,
                             const float* __restrict__ xe2,
                             const float* __restrict__ ee1,
                             const float* __restrict__ ee2,
                             const float* __restrict__ ee3,
                             int n) {
    int idx = blockIdx.x * blockDim.x + threadIdx.x;
    if (idx >= n * (D / 4)) return;
    int node = idx >> 5;
    int j    = idx & 31;
    int a = x[node * 2 + 0];
    int c = x[node * 2 + 1];
    float4 h = f4add(((const float4*)xe1)[a * 32 + j],
                     ((const float4*)xe2)[c * 32 + j]);
    float4 cv = f4add(f4add(((const float4*)(ee1 + 4 * D))[j],
                            ((const float4*)ee2)[j]),
                      ((const float4*)ee3)[j]);
    __half2 p0 = __floats2half2_rn(h.x, h.y);
    __half2 p1 = __floats2half2_rn(h.z, h.w);
    *(__half2*)(g_h16 + (long)idx * 4)     = p0;
    *(__half2*)(g_h16 + (long)idx * 4 + 2) = p1;
    ((float4*)g_agg)[idx] = f4add(h, cv);
}

// ---------------------------------------------------------------------------
// scatter: agg[col[e]] += h16[row[e]] + edge_emb(e)   (warp/edge, red.add.v4)
// ---------------------------------------------------------------------------
__global__ void scatter_kernel(const int* __restrict__ ei,
                               const int* __restrict__ ea,
                               const float* __restrict__ e1,
                               const float* __restrict__ e2,
                               const float* __restrict__ e3,
                               int e) {
    __shared__ float s1[7 * D], s2[3 * D], s3[3 * D];
    for (int i = threadIdx.x; i < 7 * D; i += blockDim.x) s1[i] = e1[i];
    for (int i = threadIdx.x; i < 3 * D; i += blockDim.x) s2[i] = e2[i];
    for (int i = threadIdx.x; i < 3 * D; i += blockDim.x) s3[i] = e3[i];
    __syncthreads();

    int lane  = threadIdx.x & 31;
    int warp  = (blockIdx.x * blockDim.x + threadIdx.x) >> 5;
    int nwarp = (gridDim.x * blockDim.x) >> 5;

    for (int ed = warp; ed < e; ed += nwarp) {
        int row = ei[ed];
        int col = ei[e + ed];
        int bt  = ea[ed * 3 + 0];
        int bd  = ea[ed * 3 + 1];
        int bb  = ea[ed * 3 + 2];
        float4 emb = f4add(f4add(*(const float4*)&s1[bt * D + lane * 4],
                                 *(const float4*)&s2[bd * D + lane * 4]),
                           *(const float4*)&s3[bb * D + lane * 4]);
        uint2 raw = *(const uint2*)(g_h16 + (long)row * D + lane * 4);
        float2 f01 = __half22float2(*(__half2*)&raw.x);
        float2 f23 = __half22float2(*(__half2*)&raw.y);
        float4 m;
        m.x = emb.x + f01.x;
        m.y = emb.y + f01.y;
        m.z = emb.z + f23.x;
        m.w = emb.w + f23.y;
        float* p = g_agg + (long)col * D + lane * 4;
        asm volatile("red.global.add.v4.f32 [%0], {%1,%2,%3,%4};"
                     :: "l"(p), "f"(m.x), "f"(m.y), "f"(m.z), "f"(m.w)
                     : "memory");
    }
}

// ---------------------------------------------------------------------------
// mma.sync fused GIN MLP v7: register-direct epilogues, 7 barriers,
// cp.async W loads overlapped with conversion
// ---------------------------------------------------------------------------
__global__ void __launch_bounds__(NTHR, 2)
mlp_kernel(int l, int last,
           const float* __restrict__ b1g, const float* __restrict__ b2g,
           const float* __restrict__ ee1, const float* __restrict__ ee2,
           const float* __restrict__ ee3,
           float* __restrict__ out, int n) {
    extern __shared__ char smem[];
    __half* sA  = (__half*)(smem + OFF_A);    // A tile; becomes T1 after phase1
    __half* sT0 = (__half*)(smem + OFF_T0);
    __half* sW  = (__half*)(smem + OFF_W);
    float* sb1 = (float*)(smem + OFF_SB1);
    float* sb2 = (float*)(smem + OFF_SB2);
    float* sc  = (float*)(smem + OFF_SC);

    int tid  = threadIdx.x;
    int wid  = tid >> 5;
    int lane = tid & 31;
    int wr = wid >> 2, wc = wid & 3;   // 3x4 warp grid, 32x32 warp tiles
    int row0 = blockIdx.x * TILE_M;

    unsigned sA_u32 = (unsigned)__cvta_generic_to_shared(sA);
    unsigned sT0_u32 = (unsigned)__cvta_generic_to_shared(sT0);
    unsigned sW_u32 = (unsigned)__cvta_generic_to_shared(sW);

    // B-fragment per-lane ldmatrix addresses (n-chunk pairs p=0,1), k=0
    int bn = (lane & 7) + ((lane >> 4) << 3);
    int bk = ((lane >> 3) & 1) * 8;
    unsigned bBase0 = sW_u32 + (((wc * 32 + 0 + bn) * LDWF + bk) * 2);
    unsigned bBase1 = sW_u32 + (((wc * 32 + 16 + bn) * LDWF + bk) * 2);

    // biases + next-layer self-loop const
    for (int i = tid; i < TWOD; i += NTHR) sb1[i] = b1g[l * TWOD + i];
    if (tid < D) {
        sb2[tid] = b2g[l * D + tid];
        float cv = 0.f;
        if (!last) {
            int ln = l + 1;
            cv = ee1[(ln * 7 + 4) * D + tid] + ee2[ln * 3 * D + tid]
               + ee3[ln * 3 * D + tid];
        }
        sc[tid] = cv;
    }

    // kick W1 h0 cp.async first (overlaps with A load)
    for (int i = tid; i < 2048; i += NTHR) {
        int nn = i >> 4, k8 = i & 15;
        long src = ((long)(l * TWOD + nn)) * D + k8 * 8;
        CP_ASYNC16(sW_u32 + (nn * LDWF + k8 * 8) * 2, g_w1t + src);
    }

    // ---- load A tile fp32 -> fp16 smem ----
    for (int i = tid; i < TILE_M * (D / 4); i += NTHR) {  // 3072
        int r = i / 32, c4 = i & 31;
        float4 v = make_float4(0.f, 0.f, 0.f, 0.f);
        if (row0 + r < n)
            v = *(const float4*)(g_agg + ((long)(row0 + r)) * D + c4 * 4);
        __half2 p0 = __floats2half2_rn(v.x, v.y);
        __half2 p1 = __floats2half2_rn(v.z, v.w);
        *(__half2*)(sA + r * LDA + c4 * 4)     = p0;
        *(__half2*)(sA + r * LDA + c4 * 4 + 2) = p1;
    }
    CP_ASYNC_WAIT_ALL();
    __syncthreads();                                   // S1

    int cl = (lane & 3) * 2;       // acc col within n8 tile
    int rl = lane >> 2;            // acc row within m16 tile (and +8)

    // ================= PHASE 1 h=0 : C = A @ W1[:,0:128] =================
    float acc1[2][4][4];
#pragma unroll
    for (int i = 0; i < 2; ++i)
#pragma unroll
        for (int j = 0; j < 4; ++j)
#pragma unroll
            for (int q = 0; q < 4; ++q) acc1[i][j][q] = 0.f;

    warp_gemm(acc1, sA_u32 + (wr * 32) * LDA * 2, bBase0, bBase1, lane);
    __syncthreads();                                   // S2 (all sW reads done)

    // issue W1 h1 cp.async, then convert h0 (overlap)
    for (int i = tid; i < 2048; i += NTHR) {
        int nn = i >> 4, k8 = i & 15;
        long src = ((long)(l * TWOD + 128 + nn)) * D + k8 * 8;
        CP_ASYNC16(sW_u32 + (nn * LDWF + k8 * 8) * 2, g_w1t + src);
    }
#pragma unroll
    for (int i = 0; i < 2; ++i)
#pragma unroll
        for (int j = 0; j < 4; ++j) {
            int colb = wc * 32 + j * 8 + cl;
            int r = wr * 32 + i * 16 + rl;
            float t0 = fmaxf(acc1[i][j][0] + sb1[colb], 0.f);
            float t1 = fmaxf(acc1[i][j][1] + sb1[colb + 1], 0.f);
            *(__half2*)&sT0[r * LDA + colb] = __floats2half2_rn(t0, t1);
            t0 = fmaxf(acc1[i][j][2] + sb1[colb], 0.f);
            t1 = fmaxf(acc1[i][j][3] + sb1[colb + 1], 0.f);
            *(__half2*)&sT0[(r + 8) * LDA + colb] = __floats2half2_rn(t0, t1);
        }
    CP_ASYNC_WAIT_ALL();
    __syncthreads();                                   // S3

    // ================= PHASE 1 h=1 : C = A @ W1[:,128:256] =================
#pragma unroll
    for (int i = 0; i < 2; ++i)
#pragma unroll
        for (int j = 0; j < 4; ++j)
#pragma unroll
            for (int q = 0; q < 4; ++q) acc1[i][j][q] = 0.f;

    warp_gemm(acc1, sA_u32 + (wr * 32) * LDA * 2, bBase0, bBase1, lane);
    __syncthreads();                                   // S4 (sA + sW reads done)

    // issue W2 kc0 cp.async, then convert h1 into sA (=T1) (overlap)
    for (int i = tid; i < 2048; i += NTHR) {
        int nn = i >> 4, k8 = i & 15;
        long src = ((long)(l * D + nn)) * TWOD + k8 * 8;
        CP_ASYNC16(sW_u32 + (nn * LDWF + k8 * 8) * 2, g_w2t + src);
    }
#pragma unroll
    for (int i = 0; i < 2; ++i)
#pragma unroll
        for (int j = 0; j < 4; ++j) {
            int colb = wc * 32 + j * 8 + cl;
            int r = wr * 32 + i * 16 + rl;
            float t0 = fmaxf(acc1[i][j][0] + sb1[128 + colb], 0.f);
            float t1 = fmaxf(acc1[i][j][1] + sb1[128 + colb + 1], 0.f);
            *(__half2*)&sA[r * LDA + colb] = __floats2half2_rn(t0, t1);
            t0 = fmaxf(acc1[i][j][2] + sb1[128 + colb], 0.f);
            t1 = fmaxf(acc1[i][j][3] + sb1[128 + colb + 1], 0.f);
            *(__half2*)&sA[(r + 8) * LDA + colb] = __floats2half2_rn(t0, t1);
        }
    CP_ASYNC_WAIT_ALL();
    __syncthreads();                                   // S5

    // ================= PHASE 2 : C2 = T @ W2 (kc0 from T0, kc1 from T1) ====
    float acc2[2][4][4];
#pragma unroll
    for (int i = 0; i < 2; ++i)
#pragma unroll
        for (int j = 0; j < 4; ++j)
#pragma unroll
            for (int q = 0; q < 4; ++q) acc2[i][j][q] = 0.f;

    warp_gemm(acc2, sT0_u32 + (wr * 32) * LDA * 2, bBase0, bBase1, lane);
    __syncthreads();                                   // S6 (sW reads done)

    for (int i = tid; i < 2048; i += NTHR) {
        int nn = i >> 4, k8 = i & 15;
        long src = ((long)(l * D + nn)) * TWOD + 128 + k8 * 8;
        CP_ASYNC16(sW_u32 + (nn * LDWF + k8 * 8) * 2, g_w2t + src);
    }
    CP_ASYNC_WAIT_ALL();
    __syncthreads();                                   // S7

    warp_gemm(acc2, sA_u32 + (wr * 32) * LDA * 2, bBase0, bBase1, lane);

    // ---- epilogue straight from registers ----
#pragma unroll
    for (int i = 0; i < 2; ++i)
#pragma unroll
        for (int j = 0; j < 4; ++j) {
            int colb = wc * 32 + j * 8 + cl;
#pragma unroll
            for (int half = 0; half < 2; ++half) {
                int r = wr * 32 + i * 16 + rl + half * 8;
                long grow = (long)row0 + r;
                if (grow >= n) continue;
                float o0 = acc2[i][j][half * 2 + 0] + sb2[colb];
                float o1 = acc2[i][j][half * 2 + 1] + sb2[colb + 1];
                long off = grow * D + colb;
                if (last) {
                    *(float2*)(out + off) = make_float2(o0, o1);
                } else {
                    float h0 = fmaxf(o0, 0.f), h1 = fmaxf(o1, 0.f);
                    *(__half2*)(g_h16 + off) = __floats2half2_rn(h0, h1);
                    *(float2*)(g_agg + off) =
                        make_float2(h0 + sc[colb], h1 + sc[colb + 1]);
                }
            }
        }
}

// ---------------------------------------------------------------------------
extern "C" void kernel_launch(void* const* d_in, const int* in_sizes, int n_in,
                              void* d_out, int out_size) {
    const int*   x   = (const int*)d_in[0];
    const int*   ei  = (const int*)d_in[1];
    const int*   ea  = (const int*)d_in[2];
    const float* xe1 = (const float*)d_in[3];
    const float* xe2 = (const float*)d_in[4];
    const float* ee1 = (const float*)d_in[5];
    const float* ee2 = (const float*)d_in[6];
    const float* ee3 = (const float*)d_in[7];
    const float* W1  = (const float*)d_in[8];
    const float* b1  = (const float*)d_in[9];
    const float* W2  = (const float*)d_in[10];
    const float* b2  = (const float*)d_in[11];
    float* out = (float*)d_out;
    int n = in_sizes[0] / 2;   // x is [N,2]
    int e = in_sizes[1] / 2;   // edge_index is [2,E]

    cudaFuncSetAttribute(mlp_kernel,
                         cudaFuncAttributeMaxDynamicSharedMemorySize, SMEM_BYTES);

    prep_w<<<(NLAYER * TWOD * D + 255) / 256, 256>>>(W1, W2);
    embed_kernel<<<(n * (D / 4) + 255) / 256, 256>>>(x, xe1, xe2, ee1, ee2, ee3, n);

    int ntiles = (n + TILE_M - 1) / TILE_M;
    for (int l = 0; l < NLAYER; ++l) {
        scatter_kernel<<<2368, 256>>>(ei, ea,
                                      ee1 + (long)l * 7 * D,
                                      ee2 + (long)l * 3 * D,
                                      ee3 + (long)l * 3 * D, e);
        int last = (l == NLAYER - 1);
        mlp_kernel<<<ntiles, NTHR, SMEM_BYTES>>>(
            l, last, b1, b2, ee1, ee2, ee3, out, n);
    }
}